// round 8
// baseline (speedup 1.0000x reference)
#include <cuda_runtime.h>

// ---------------------------------------------------------------------------
// RealVirtualAttention:
//   1) masked segment-mean over sorted batch (real vs virtual nodes) -> [B,2,D]
//   2) HAN semantic attention: score_m = sum_b q^T tanh(W1^T x_{b,m} + b1)
//      beta = softmax(score / B)
//   3) out[b] = beta0 * mean_real[b] + beta1 * mean_virtual[b]
// ---------------------------------------------------------------------------

#define VIRTUAL_Z 100
#define MAXB 8192
#define MAXD 256
#define MAXN (1 << 22)             // mask capacity: 4M rows (16 MB)
#define SGPB 4                     // graphs per block in score kernel
#define SVPB (2*SGPB)              // vectors per block (8)
#define SB4  4                     // sub-blocks in wide seg kernel
#define SW4  96                    // threads per sub-block

typedef unsigned long long u64;

__device__ float g_means[(size_t)MAXB * 2 * MAXD];   // [B][2][D] means
__device__ float g_part[(MAXB / SGPB) * 2 + 2];      // per-block partial scores
__device__ float g_score[2];
__device__ int   g_is64;
__device__ int   g_bounds[MAXB + 1];                 // row range per graph
__device__ unsigned int g_count;                     // score-block completion ctr
__device__ float g_maskf[MAXN];                      // 1.0 = real, 0.0 = virtual

// ---- packed f32x2 helpers --------------------------------------------------
__device__ __forceinline__ u64 ld64cs(const float* p) {
    u64 v;
    asm volatile("ld.global.cs.b64 %0, [%1];" : "=l"(v) : "l"(p));
    return v;
}
__device__ __forceinline__ void ld128cs(const float* p, u64& a, u64& b) {
    asm volatile("ld.global.cs.v2.b64 {%0, %1}, [%2];"
                 : "=l"(a), "=l"(b) : "l"(p));
}
__device__ __forceinline__ void add2(u64& a, u64 b) {
    asm("add.rn.f32x2 %0, %1, %2;" : "=l"(a) : "l"(a), "l"(b));
}
__device__ __forceinline__ void fma2(u64& a, u64 m, u64 v) {
    asm("fma.rn.f32x2 %0, %1, %2, %3;" : "=l"(a) : "l"(m), "l"(v), "l"(a));
}
__device__ __forceinline__ u64 dup2(float m) {
    u64 r;
    asm("mov.b64 %0, {%1, %1};" : "=l"(r) : "f"(m));
    return r;
}
__device__ __forceinline__ float2 unpk(u64 v) {
    float2 r;
    asm("mov.b64 {%0, %1}, %2;" : "=f"(r.x), "=f"(r.y) : "l"(v));
    return r;
}

// ---------------------------------------------------------------------------
// Detect int32 vs int64 (jax silently downcasts int64 -> int32 when x64 is
// disabled): viewing as int32, odd slots near the end are 0 iff int64.
// Also resets g_count for the score kernel's last-block election.
// ---------------------------------------------------------------------------
__global__ void detect_kernel(const int* __restrict__ bat32, int N) {
    if (threadIdx.x == 0) {
        int is64 = 1;
        int idx = N - 1;
        if ((idx & 1) == 0) idx--;
        for (int k = 0; k < 8 && idx >= 1; k++, idx -= 2) {
            if (bat32[idx] != 0) { is64 = 0; break; }
        }
        g_is64 = is64;
        g_count = 0u;
    }
}

// ---------------------------------------------------------------------------
// Bounds kernel: g_bounds[b] = first row index with batch >= b.
// ---------------------------------------------------------------------------
__global__ void bounds_kernel(const int* __restrict__ bat32, int N, int B) {
    const int s = g_is64;
    const int i = blockIdx.x * blockDim.x + threadIdx.x;
    if (i >= N) return;
    const int cur  = bat32[(size_t)i << s];
    const int prev = (i == 0) ? -1 : bat32[(size_t)(i - 1) << s];
    for (int b = prev + 1; b <= cur; b++) g_bounds[b] = i;
    if (i == N - 1) {
        for (int b = cur + 1; b <= B; b++) g_bounds[b] = N;
    }
}

// ---------------------------------------------------------------------------
// Mask kernel: g_maskf[i] = (z[i] != VIRTUAL_Z) ? 1.f : 0.f, int4-vectorized.
// ---------------------------------------------------------------------------
__global__ void mask_kernel(const int* __restrict__ z32, int N) {
    const int s = g_is64;
    const int base = (blockIdx.x * blockDim.x + threadIdx.x) * 4;
    if (base >= N) return;
    if (base + 4 <= N) {
        float4 m;
        if (!s) {
            const int4 w = *reinterpret_cast<const int4*>(&z32[base]);
            m.x = (w.x != VIRTUAL_Z) ? 1.f : 0.f;
            m.y = (w.y != VIRTUAL_Z) ? 1.f : 0.f;
            m.z = (w.z != VIRTUAL_Z) ? 1.f : 0.f;
            m.w = (w.w != VIRTUAL_Z) ? 1.f : 0.f;
        } else {
            const int4 a = *reinterpret_cast<const int4*>(&z32[2 * base]);
            const int4 c = *reinterpret_cast<const int4*>(&z32[2 * base + 4]);
            m.x = (a.x != VIRTUAL_Z) ? 1.f : 0.f;
            m.y = (a.z != VIRTUAL_Z) ? 1.f : 0.f;
            m.z = (c.x != VIRTUAL_Z) ? 1.f : 0.f;
            m.w = (c.z != VIRTUAL_Z) ? 1.f : 0.f;
        }
        *reinterpret_cast<float4*>(&g_maskf[base]) = m;
    } else {
        for (int k = base; k < N; k++) {
            const int zz = z32[(size_t)k << s];
            g_maskf[k] = (zz != VIRTUAL_Z) ? 1.f : 0.f;
        }
    }
}

// ---------------------------------------------------------------------------
// Kernel 1 (hot), wide variant: 384 threads = 4 sub-blocks of 96.
// Row-pair float4 streaming (two rows = D/2 float4s, 16B-aligned for even
// global row). Each 16-row chunk: sub-block j handles pairs 2j, 2j+1 ->
// 2 LDG.128 per thread per iteration, 48 warps/SM resident. Packed f32x2
// masked accumulation (mask m per row, selected per packed half by a
// per-thread constant). Sub-block partials merged via SMEM in fixed order;
// prologue (align rows to %4) and tail (<16 rows) handled by sub-block 0.
// sv = st - sr; counts from mask sums.
// ---------------------------------------------------------------------------
template <int PQS>   // PQ = D/2 (float4s per pair block); 0 = runtime
__global__ void __launch_bounds__(SB4 * SW4)
seg_mean_pair4(const float* __restrict__ x, int D, int PQrt) {
    const int PQ = (PQS > 0) ? PQS : PQrt;
    const int b = blockIdx.x;
    const int start = g_bounds[b];
    const int end   = g_bounds[b + 1];
    const int tid = threadIdx.x;
    const int sb  = tid / SW4;
    const int t   = tid - sb * SW4;             // 0..95
    const bool act = (t < PQ);
    const int  tc  = act ? t : (PQ - 1);        // clamp: no divergence

    const bool lowR0  = (4 * tc + 1 < D);       // low packed half in row 0 of pair?
    const bool highR0 = (4 * tc + 3 < D);       // high packed half in row 0 of pair?

    u64 stL = 0ull, srL = 0ull, stH = 0ull, srH = 0ull;  // pair-loop accs
    u64 stP = 0ull, srP = 0ull;                 // scalar accs (feat 2tc, 2tc+1)
    float crf = 0.f;

    // Prologue: rows [start, first) handled scalar by sub-block 0.
    const int first = min(end, (start + 3) & ~3);
    if (sb == 0) {
        for (int r = start; r < first; r++) {
            const float m = g_maskf[r];
            const u64 v = ld64cs(x + (size_t)r * D + 2 * tc);
            add2(stP, v); fma2(srP, dup2(m), v); crf += m;
        }
    }

    // Main: 16 rows per iteration; sub-block sb owns rows [i+4sb, i+4sb+4).
    int i = first;
    const float* xp = x + ((size_t)i + 4 * sb) * D + 4 * tc;
    for (; i + 16 <= end; i += 16, xp += (size_t)16 * D) {
        const float4 m = *reinterpret_cast<const float4*>(&g_maskf[i + 4 * sb]);
        u64 vl0, vh0, vl1, vh1;
        ld128cs(xp, vl0, vh0);
        ld128cs(xp + (size_t)2 * D, vl1, vh1);
        const u64 d0 = dup2(m.x), d1 = dup2(m.y);
        const u64 d2 = dup2(m.z), d3 = dup2(m.w);
        add2(stL, vl0); fma2(srL, lowR0  ? d0 : d1, vl0);
        add2(stH, vh0); fma2(srH, highR0 ? d0 : d1, vh0);
        add2(stL, vl1); fma2(srL, lowR0  ? d2 : d3, vl1);
        add2(stH, vh1); fma2(srH, highR0 ? d2 : d3, vh1);
        crf += m.x + m.y + m.z + m.w;
    }

    // Tail (<16 rows, i multiple of 4): sub-block 0 only.
    if (sb == 0) {
        int r = i;
        const float* tp = x + (size_t)r * D + 4 * tc;
        for (; r + 2 <= end; r += 2, tp += (size_t)2 * D) {
            const float m0 = g_maskf[r];
            const float m1 = g_maskf[r + 1];
            u64 a, c;
            ld128cs(tp, a, c);
            const u64 e0 = dup2(m0), e1 = dup2(m1);
            add2(stL, a); fma2(srL, lowR0  ? e0 : e1, a);
            add2(stH, c); fma2(srH, highR0 ? e0 : e1, c);
            crf += m0 + m1;
        }
        for (; r < end; r++) {
            const float m = g_maskf[r];
            const u64 v = ld64cs(x + (size_t)r * D + 2 * tc);
            add2(stP, v); fma2(srP, dup2(m), v); crf += m;
        }
    }

    // Merge sub-block partials (fixed order -> deterministic) and undo the
    // pair-block feature permutation.
    __shared__ float sst[SB4][2 * MAXD];
    __shared__ float ssr[SB4][2 * MAXD];
    __shared__ float scnt[SB4];
    if (act) {
        const float2 l = unpk(stL), h = unpk(stH);
        sst[sb][4 * t + 0] = l.x; sst[sb][4 * t + 1] = l.y;
        sst[sb][4 * t + 2] = h.x; sst[sb][4 * t + 3] = h.y;
        const float2 rl = unpk(srL), rh = unpk(srH);
        ssr[sb][4 * t + 0] = rl.x; ssr[sb][4 * t + 1] = rl.y;
        ssr[sb][4 * t + 2] = rh.x; ssr[sb][4 * t + 3] = rh.y;
    }
    if (t == 0) scnt[sb] = crf;
    __syncthreads();

    if (sb == 0 && act) {
        const float2 pst = unpk(stP), psr = unpk(srP);
        const int f0 = 2 * t, f1 = 2 * t + 1;
        float st0 = pst.x, st1 = pst.y, sr0 = psr.x, sr1 = psr.y;
        #pragma unroll
        for (int j = 0; j < SB4; j++) {
            st0 += sst[j][f0] + sst[j][f0 + D];
            st1 += sst[j][f1] + sst[j][f1 + D];
            sr0 += ssr[j][f0] + ssr[j][f0 + D];
            sr1 += ssr[j][f1] + ssr[j][f1 + D];
        }
        const float cr = scnt[0] + scnt[1] + scnt[2] + scnt[3];
        const float cv = (float)(end - start) - cr;
        const float ir = 1.f / fmaxf(cr, 1.f);
        const float iv = 1.f / fmaxf(cv, 1.f);
        float* mr = g_means + (size_t)b * 2 * D;
        reinterpret_cast<float2*>(mr)[t]     = make_float2(sr0 * ir, sr1 * ir);
        reinterpret_cast<float2*>(mr + D)[t] = make_float2((st0 - sr0) * iv,
                                                           (st1 - sr1) * iv);
    }
}

// Scalar fallback for odd D or PQ > 96 (not hit for this problem's shapes).
__global__ void seg_mean_scalar_kernel(const float* __restrict__ x,
                                       const int*   __restrict__ z32,
                                       int D) {
    const int b = blockIdx.x;
    const int s = g_is64;
    const int start = g_bounds[b];
    const int end   = g_bounds[b + 1];
    const int t = threadIdx.x;

    float srs = 0.f, svs = 0.f;
    int cr = 0, cv = 0;
    for (int i = start; i < end; i++) {
        const int zz = z32[(size_t)i << s];
        float v = (t < D) ? x[(size_t)i * D + t] : 0.f;
        if (zz != VIRTUAL_Z) { srs += v; cr++; } else { svs += v; cv++; }
    }
    if (t < D) {
        float* mr = g_means + (size_t)b * 2 * D;
        mr[t]     = srs / (float)max(cr, 1);
        mr[D + t] = svs / (float)max(cv, 1);
    }
}

// ---------------------------------------------------------------------------
// Kernel 2: semantic attention scores (best measured config).
// Block = 128 threads; each thread owns one aa column. SGPB=4 graphs
// (SVPB=8 vectors) per block. W1 stays L1/L2-resident. Last block
// (atomic-counter elect) does the fixed-order final reduction.
// ---------------------------------------------------------------------------
__global__ void score_kernel(const float* __restrict__ W1,
                             const float* __restrict__ b1,
                             const float* __restrict__ q,
                             int D, int Dp, int A, int B, int nblk) {
    extern __shared__ float sx[];   // [SVPB][Dp]
    __shared__ float r0[4], r1[4];
    __shared__ int   s_last;

    const int b0 = blockIdx.x * SGPB;
    const int nv = min(SVPB, 2 * (B - b0));   // valid vectors in this block

    for (int i = threadIdx.x; i < SVPB * Dp; i += blockDim.x) {
        const int v = i / Dp;
        const int d = i - v * Dp;
        float val = 0.f;
        if (v < nv && d < D) val = g_means[((size_t)b0 * 2 + v) * D + d];
        sx[i] = val;
    }
    if (threadIdx.x == 0) s_last = 0;
    __syncthreads();

    const int warp = threadIdx.x >> 5;
    const int lane = threadIdx.x & 31;
    float t0 = 0.f, t1 = 0.f;

    for (int aa = threadIdx.x; aa < A; aa += blockDim.x) {
        float acc[SVPB];
        const float bb = b1[aa];
        #pragma unroll
        for (int v = 0; v < SVPB; v++) acc[v] = bb;

        for (int d = 0; d < Dp; d += 4) {
            const float w0 = (d + 0 < D) ? W1[(size_t)(d + 0) * A + aa] : 0.f;
            const float w1 = (d + 1 < D) ? W1[(size_t)(d + 1) * A + aa] : 0.f;
            const float w2 = (d + 2 < D) ? W1[(size_t)(d + 2) * A + aa] : 0.f;
            const float w3 = (d + 3 < D) ? W1[(size_t)(d + 3) * A + aa] : 0.f;
            #pragma unroll
            for (int v = 0; v < SVPB; v++) {
                const float4 xv = *reinterpret_cast<const float4*>(&sx[v * Dp + d]);
                acc[v] = fmaf(xv.x, w0, acc[v]);
                acc[v] = fmaf(xv.y, w1, acc[v]);
                acc[v] = fmaf(xv.z, w2, acc[v]);
                acc[v] = fmaf(xv.w, w3, acc[v]);
            }
        }

        const float qa = q[aa];
        #pragma unroll
        for (int v = 0; v < SVPB; v++) {
            if (v < nv) {
                const float tv = tanhf(acc[v]) * qa;
                if (v & 1) t1 += tv; else t0 += tv;
            }
        }
    }

    #pragma unroll
    for (int off = 16; off; off >>= 1) {
        t0 += __shfl_down_sync(0xffffffffu, t0, off);
        t1 += __shfl_down_sync(0xffffffffu, t1, off);
    }
    if (lane == 0) { r0[warp] = t0; r1[warp] = t1; }
    __syncthreads();

    if (threadIdx.x == 0) {
        float s0 = r0[0] + r0[1] + r0[2] + r0[3];
        float s1 = r1[0] + r1[1] + r1[2] + r1[3];
        g_part[2 * blockIdx.x + 0] = s0;
        g_part[2 * blockIdx.x + 1] = s1;
        __threadfence();
        const unsigned int done = atomicAdd(&g_count, 1u);
        if (done == (unsigned int)(nblk - 1)) s_last = 1;
    }
    __syncthreads();

    if (s_last && warp == 0) {
        float a0 = 0.f, a1 = 0.f;
        for (int i = lane; i < nblk; i += 32) {
            a0 += g_part[2 * i + 0];
            a1 += g_part[2 * i + 1];
        }
        #pragma unroll
        for (int off = 16; off; off >>= 1) {
            a0 += __shfl_down_sync(0xffffffffu, a0, off);
            a1 += __shfl_down_sync(0xffffffffu, a1, off);
        }
        if (lane == 0) { g_score[0] = a0; g_score[1] = a1; }
    }
}

// ---------------------------------------------------------------------------
// Kernel 3: beta = softmax(score / B); out[b,d] = beta0*mean_r + beta1*mean_v
// One block per graph: no integer division, float2 I/O.
// ---------------------------------------------------------------------------
__global__ void combine_graph_kernel(float2* __restrict__ outp, int D) {
    const float invB = 1.f / (float)gridDim.x;
    const float s0 = g_score[0] * invB;
    const float s1 = g_score[1] * invB;
    const float mx = fmaxf(s0, s1);
    const float e0 = expf(s0 - mx);
    const float e1 = expf(s1 - mx);
    const float beta0 = e0 / (e0 + e1);
    const float beta1 = 1.f - beta0;

    const int b  = blockIdx.x;
    const int t  = threadIdx.x;
    const int D2 = D >> 1;
    if (t < D2) {
        const float* mrow = g_means + (size_t)b * 2 * D;
        const float2 r = reinterpret_cast<const float2*>(mrow)[t];
        const float2 v = reinterpret_cast<const float2*>(mrow + D)[t];
        outp[(size_t)b * D2 + t] = make_float2(r.x * beta0 + v.x * beta1,
                                               r.y * beta0 + v.y * beta1);
    }
}

__global__ void combine_scalar_kernel(float* __restrict__ outp, int B, int D) {
    const float invB = 1.f / (float)B;
    const float s0 = g_score[0] * invB;
    const float s1 = g_score[1] * invB;
    const float mx = fmaxf(s0, s1);
    const float e0 = expf(s0 - mx);
    const float e1 = expf(s1 - mx);
    const float beta0 = e0 / (e0 + e1);
    const float beta1 = 1.f - beta0;

    const int idx = blockIdx.x * blockDim.x + threadIdx.x;
    const int tot = B * D;
    if (idx < tot) {
        const int b = idx / D;
        const int d = idx - b * D;
        const float* mr = g_means + (size_t)b * 2 * D;
        outp[idx] = mr[d] * beta0 + mr[D + d] * beta1;
    }
}

// ---------------------------------------------------------------------------
extern "C" void kernel_launch(void* const* d_in, const int* in_sizes, int n_in,
                              void* d_out, int out_size) {
    const float* x   = (const float*)d_in[0];   // out [N, D] fp32
    const int*   z   = (const int*)d_in[1];     // z   [N] int32/int64
    const int*   bat = (const int*)d_in[2];     // batch [N] sorted int32/int64
    const float* W1  = (const float*)d_in[3];   // [D, A]
    const float* b1  = (const float*)d_in[4];   // [A]
    const float* q   = (const float*)d_in[5];   // [A, 1]

    const int N = in_sizes[1];
    const int D = in_sizes[0] / N;
    const int A = in_sizes[4];
    const int B = out_size / D;

    detect_kernel<<<1, 32>>>(bat, N);                        // launch 1
    bounds_kernel<<<(N + 255) / 256, 256>>>(bat, N, B);      // launch 2
    mask_kernel<<<(N / 4 + 256) / 256, 256>>>(z, N);         // launch 3

    const int PQ = D >> 1;                                   // float4s per pair
    const bool fast = ((D & 1) == 0) && (N <= MAXN) && (D <= MAXD) && (PQ <= SW4);
    if (fast) {                                              // launch 4 (profiled)
        if (PQ == 75) seg_mean_pair4<75><<<B, SB4 * SW4>>>(x, D, PQ);
        else          seg_mean_pair4<0><<<B, SB4 * SW4>>>(x, D, PQ);
    } else {
        int tpb = ((D + 31) / 32) * 32;
        if (tpb > 1024) tpb = 1024;
        seg_mean_scalar_kernel<<<B, tpb>>>(x, z, D);
    }

    const int Dp = (D + 3) & ~3;
    const int nblk2 = (B + SGPB - 1) / SGPB;
    const size_t shmem = (size_t)SVPB * Dp * sizeof(float);
    score_kernel<<<nblk2, 128, shmem>>>(W1, b1, q, D, Dp, A, B, nblk2);  // 5

    if ((D & 1) == 0) {                                      // launch 6
        const int D2 = D >> 1;
        int tpb = ((D2 + 31) / 32) * 32;
        if (tpb > 1024) tpb = 1024;
        combine_graph_kernel<<<B, tpb>>>((float2*)d_out, D);
    } else {
        const int tot = B * D;
        combine_scalar_kernel<<<(tot + 255) / 256, 256>>>((float*)d_out, B, D);
    }
}

// round 9
// speedup vs baseline: 1.0444x; 1.0444x over previous
#include <cuda_runtime.h>

// ---------------------------------------------------------------------------
// RealVirtualAttention:
//   1) masked segment-mean over sorted batch (real vs virtual nodes) -> [B,2,D]
//   2) HAN semantic attention: score_m = sum_b q^T tanh(W1^T x_{b,m} + b1)
//      beta = softmax(score / B)
//   3) out[b] = beta0 * mean_real[b] + beta1 * mean_virtual[b]
// ---------------------------------------------------------------------------

#define VIRTUAL_Z 100
#define MAXB 8192
#define MAXD 256
#define MAXN (1 << 22)             // mask capacity: 4M rows (16 MB)
#define SGPB 4                     // graphs per block in score kernel
#define SVPB (2*SGPB)              // vectors per block (8)
#define NSPLIT 2                   // row-range splits per graph in seg kernel

typedef unsigned long long u64;

__device__ float g_means[(size_t)MAXB * 2 * MAXD];     // [B][2][D] means
__device__ float g_pst[(size_t)NSPLIT * MAXB * MAXD];  // per-part total sums
__device__ float g_psr[(size_t)NSPLIT * MAXB * MAXD];  // per-part real sums
__device__ float g_pcnt[NSPLIT * MAXB];                // per-part real counts
__device__ float g_part[(MAXB / SGPB) * 2 + 2];        // per-block partial scores
__device__ float g_score[2];
__device__ int   g_is64;
__device__ int   g_bounds[MAXB + 1];                   // row range per graph
__device__ unsigned int g_count;                       // score completion ctr
__device__ float g_maskf[MAXN];                        // 1.0 = real, 0.0 = virtual

// ---- packed f32x2 helpers --------------------------------------------------
__device__ __forceinline__ u64 ld64cs(const float* p) {
    u64 v;
    asm volatile("ld.global.cs.b64 %0, [%1];" : "=l"(v) : "l"(p));
    return v;
}
__device__ __forceinline__ void ld128cs(const float* p, u64& a, u64& b) {
    asm volatile("ld.global.cs.v2.b64 {%0, %1}, [%2];"
                 : "=l"(a), "=l"(b) : "l"(p));
}
__device__ __forceinline__ void add2(u64& a, u64 b) {
    asm("add.rn.f32x2 %0, %1, %2;" : "=l"(a) : "l"(a), "l"(b));
}
__device__ __forceinline__ void fma2(u64& a, u64 m, u64 v) {
    asm("fma.rn.f32x2 %0, %1, %2, %3;" : "=l"(a) : "l"(m), "l"(v), "l"(a));
}
__device__ __forceinline__ u64 dup2(float m) {
    u64 r;
    asm("mov.b64 %0, {%1, %1};" : "=l"(r) : "f"(m));
    return r;
}
__device__ __forceinline__ float2 unpk(u64 v) {
    float2 r;
    asm("mov.b64 {%0, %1}, %2;" : "=f"(r.x), "=f"(r.y) : "l"(v));
    return r;
}

// ---------------------------------------------------------------------------
// Detect int32 vs int64 (jax silently downcasts int64 -> int32 when x64 is
// disabled): viewing as int32, odd slots near the end are 0 iff int64.
// Also resets g_count for the score kernel's last-block election.
// ---------------------------------------------------------------------------
__global__ void detect_kernel(const int* __restrict__ bat32, int N) {
    if (threadIdx.x == 0) {
        int is64 = 1;
        int idx = N - 1;
        if ((idx & 1) == 0) idx--;
        for (int k = 0; k < 8 && idx >= 1; k++, idx -= 2) {
            if (bat32[idx] != 0) { is64 = 0; break; }
        }
        g_is64 = is64;
        g_count = 0u;
    }
}

// ---------------------------------------------------------------------------
// Bounds kernel: g_bounds[b] = first row index with batch >= b.
// ---------------------------------------------------------------------------
__global__ void bounds_kernel(const int* __restrict__ bat32, int N, int B) {
    const int s = g_is64;
    const int i = blockIdx.x * blockDim.x + threadIdx.x;
    if (i >= N) return;
    const int cur  = bat32[(size_t)i << s];
    const int prev = (i == 0) ? -1 : bat32[(size_t)(i - 1) << s];
    for (int b = prev + 1; b <= cur; b++) g_bounds[b] = i;
    if (i == N - 1) {
        for (int b = cur + 1; b <= B; b++) g_bounds[b] = N;
    }
}

// ---------------------------------------------------------------------------
// Mask kernel: g_maskf[i] = (z[i] != VIRTUAL_Z) ? 1.f : 0.f, int4-vectorized.
// ---------------------------------------------------------------------------
__global__ void mask_kernel(const int* __restrict__ z32, int N) {
    const int s = g_is64;
    const int base = (blockIdx.x * blockDim.x + threadIdx.x) * 4;
    if (base >= N) return;
    if (base + 4 <= N) {
        float4 m;
        if (!s) {
            const int4 w = *reinterpret_cast<const int4*>(&z32[base]);
            m.x = (w.x != VIRTUAL_Z) ? 1.f : 0.f;
            m.y = (w.y != VIRTUAL_Z) ? 1.f : 0.f;
            m.z = (w.z != VIRTUAL_Z) ? 1.f : 0.f;
            m.w = (w.w != VIRTUAL_Z) ? 1.f : 0.f;
        } else {
            const int4 a = *reinterpret_cast<const int4*>(&z32[2 * base]);
            const int4 c = *reinterpret_cast<const int4*>(&z32[2 * base + 4]);
            m.x = (a.x != VIRTUAL_Z) ? 1.f : 0.f;
            m.y = (a.z != VIRTUAL_Z) ? 1.f : 0.f;
            m.z = (c.x != VIRTUAL_Z) ? 1.f : 0.f;
            m.w = (c.z != VIRTUAL_Z) ? 1.f : 0.f;
        }
        *reinterpret_cast<float4*>(&g_maskf[base]) = m;
    } else {
        for (int k = base; k < N; k++) {
            const int zz = z32[(size_t)k << s];
            g_maskf[k] = (zz != VIRTUAL_Z) ? 1.f : 0.f;
        }
    }
}

// ---------------------------------------------------------------------------
// Kernel 1 (hot): R7 row-pair float4 streaming body, but each graph's rows
// are split across NSPLIT blocks (block = (graph, part)). Per-thread MLP is
// unchanged (8 LDG.128 in flight); the per-block work unit halves, cutting
// the last-wave tail. Partial sums (natural feature order via the SMEM
// transpose) + real-count are written to scratch; finalize_kernel merges.
// ---------------------------------------------------------------------------
template <int PQS>   // PQ = D/2 (float4s per pair block); 0 = runtime
__global__ void seg_mean_part(const float* __restrict__ x, int D, int PQrt) {
    const int PQ = (PQS > 0) ? PQS : PQrt;
    const int bid = blockIdx.x;
    const int b = bid / NSPLIT;
    const int p = bid - b * NSPLIT;
    const int gs = g_bounds[b];
    const int ge = g_bounds[b + 1];
    const int len = ge - gs;
    const int per = (len + NSPLIT - 1) / NSPLIT;
    const int start = min(ge, gs + p * per);
    const int end   = min(ge, start + per);

    const int t   = threadIdx.x;
    const bool act = (t < PQ);
    const int  tc  = act ? t : (PQ - 1);        // clamp: no divergence

    const bool lowR0  = (4 * tc + 1 < D);       // low packed half in row 0?
    const bool highR0 = (4 * tc + 3 < D);       // high packed half in row 0?

    u64 stL = 0ull, srL = 0ull, stH = 0ull, srH = 0ull;  // pair-loop accs
    u64 stP = 0ull, srP = 0ull;                 // scalar accs (feat 2tc,2tc+1)
    float crf = 0.f;

    int i = start;
    // Scalar prologue: align i to a multiple of 4.
    for (; i < end && (i & 3); i++) {
        const float m = g_maskf[i];
        const u64 v = ld64cs(x + (size_t)i * D + 2 * tc);
        add2(stP, v); fma2(srP, dup2(m), v); crf += m;
    }

    const float* xp = x + (size_t)i * D + 4 * tc;
    // Main: 16 rows = 8 pairs per iteration (8 LDG.128 in flight per thread).
    for (; i + 16 <= end; i += 16, xp += (size_t)16 * D) {
        float4 mq[4];
        #pragma unroll
        for (int j = 0; j < 4; j++)
            mq[j] = *reinterpret_cast<const float4*>(&g_maskf[i + 4 * j]);
        u64 vl[8], vh[8];
        #pragma unroll
        for (int k = 0; k < 8; k++)
            ld128cs(xp + (size_t)2 * k * D, vl[k], vh[k]);

        #pragma unroll
        for (int k = 0; k < 8; k++) {
            const float4 mk = mq[k >> 1];
            const float m0 = (k & 1) ? mk.z : mk.x;
            const float m1 = (k & 1) ? mk.w : mk.y;
            const u64 d0 = dup2(m0), d1 = dup2(m1);
            add2(stL, vl[k]); fma2(srL, lowR0  ? d0 : d1, vl[k]);
            add2(stH, vh[k]); fma2(srH, highR0 ? d0 : d1, vh[k]);
        }
        crf += mq[0].x + mq[0].y + mq[0].z + mq[0].w
             + mq[1].x + mq[1].y + mq[1].z + mq[1].w
             + mq[2].x + mq[2].y + mq[2].z + mq[2].w
             + mq[3].x + mq[3].y + mq[3].z + mq[3].w;
    }
    // Tail pairs (i still even).
    for (; i + 2 <= end; i += 2, xp += (size_t)2 * D) {
        const float m0 = g_maskf[i];
        const float m1 = g_maskf[i + 1];
        u64 a, c;
        ld128cs(xp, a, c);
        const u64 d0 = dup2(m0), d1 = dup2(m1);
        add2(stL, a); fma2(srL, lowR0  ? d0 : d1, a);
        add2(stH, c); fma2(srH, highR0 ? d0 : d1, c);
        crf += m0 + m1;
    }
    // Final odd row.
    for (; i < end; i++) {
        const float m = g_maskf[i];
        const u64 v = ld64cs(x + (size_t)i * D + 2 * tc);
        add2(stP, v); fma2(srP, dup2(m), v); crf += m;
    }

    // Undo the pair-block feature permutation via SMEM; fold the two row
    // positions of each pair together; add scalar-path partials; store.
    __shared__ float sst[2 * MAXD], ssr[2 * MAXD];
    if (act) {
        const float2 l = unpk(stL), h = unpk(stH);
        sst[4 * t + 0] = l.x; sst[4 * t + 1] = l.y;
        sst[4 * t + 2] = h.x; sst[4 * t + 3] = h.y;
        const float2 rl = unpk(srL), rh = unpk(srH);
        ssr[4 * t + 0] = rl.x; ssr[4 * t + 1] = rl.y;
        ssr[4 * t + 2] = rh.x; ssr[4 * t + 3] = rh.y;
    }
    __syncthreads();

    if (act) {
        const float2 pst = unpk(stP), psr = unpk(srP);
        const int f0 = 2 * t, f1 = 2 * t + 1;
        const float st0 = sst[f0] + sst[f0 + D] + pst.x;
        const float st1 = sst[f1] + sst[f1 + D] + pst.y;
        const float sr0 = ssr[f0] + ssr[f0 + D] + psr.x;
        const float sr1 = ssr[f1] + ssr[f1 + D] + psr.y;
        float* pst_out = g_pst + (size_t)bid * MAXD;
        float* psr_out = g_psr + (size_t)bid * MAXD;
        reinterpret_cast<float2*>(pst_out)[t] = make_float2(st0, st1);
        reinterpret_cast<float2*>(psr_out)[t] = make_float2(sr0, sr1);
        if (t == 0) g_pcnt[bid] = crf;
    }
}

// ---------------------------------------------------------------------------
// Finalize: merge NSPLIT partials per graph into g_means (fixed order).
// ---------------------------------------------------------------------------
__global__ void finalize_kernel(int D) {
    const int b = blockIdx.x;
    const int t = threadIdx.x;
    const int D2 = D >> 1;
    if (t >= D2) return;

    float st0 = 0.f, st1 = 0.f, sr0 = 0.f, sr1 = 0.f, cr = 0.f;
    #pragma unroll
    for (int p = 0; p < NSPLIT; p++) {
        const int bid = b * NSPLIT + p;
        const float2 s = reinterpret_cast<const float2*>(g_pst + (size_t)bid * MAXD)[t];
        const float2 r = reinterpret_cast<const float2*>(g_psr + (size_t)bid * MAXD)[t];
        st0 += s.x; st1 += s.y; sr0 += r.x; sr1 += r.y;
        cr += g_pcnt[bid];
    }
    const float len = (float)(g_bounds[b + 1] - g_bounds[b]);
    const float cv = len - cr;
    const float ir = 1.f / fmaxf(cr, 1.f);
    const float iv = 1.f / fmaxf(cv, 1.f);
    float* mr = g_means + (size_t)b * 2 * D;
    reinterpret_cast<float2*>(mr)[t]     = make_float2(sr0 * ir, sr1 * ir);
    reinterpret_cast<float2*>(mr + D)[t] = make_float2((st0 - sr0) * iv,
                                                       (st1 - sr1) * iv);
}

// Scalar fallback for odd D or PQ > 96 (not hit for this problem's shapes).
__global__ void seg_mean_scalar_kernel(const float* __restrict__ x,
                                       const int*   __restrict__ z32,
                                       int D) {
    const int b = blockIdx.x;
    const int s = g_is64;
    const int start = g_bounds[b];
    const int end   = g_bounds[b + 1];
    const int t = threadIdx.x;

    float srs = 0.f, svs = 0.f;
    int cr = 0, cv = 0;
    for (int i = start; i < end; i++) {
        const int zz = z32[(size_t)i << s];
        float v = (t < D) ? x[(size_t)i * D + t] : 0.f;
        if (zz != VIRTUAL_Z) { srs += v; cr++; } else { svs += v; cv++; }
    }
    if (t < D) {
        float* mr = g_means + (size_t)b * 2 * D;
        mr[t]     = srs / (float)max(cr, 1);
        mr[D + t] = svs / (float)max(cv, 1);
    }
}

// ---------------------------------------------------------------------------
// Kernel 2: semantic attention scores (best measured config).
// Block = 128 threads; each thread owns one aa column. SGPB=4 graphs
// (SVPB=8 vectors) per block. W1 stays L1/L2-resident. Last block
// (atomic-counter elect) does the fixed-order final reduction.
// ---------------------------------------------------------------------------
__global__ void score_kernel(const float* __restrict__ W1,
                             const float* __restrict__ b1,
                             const float* __restrict__ q,
                             int D, int Dp, int A, int B, int nblk) {
    extern __shared__ float sx[];   // [SVPB][Dp]
    __shared__ float r0[4], r1[4];
    __shared__ int   s_last;

    const int b0 = blockIdx.x * SGPB;
    const int nv = min(SVPB, 2 * (B - b0));   // valid vectors in this block

    for (int i = threadIdx.x; i < SVPB * Dp; i += blockDim.x) {
        const int v = i / Dp;
        const int d = i - v * Dp;
        float val = 0.f;
        if (v < nv && d < D) val = g_means[((size_t)b0 * 2 + v) * D + d];
        sx[i] = val;
    }
    if (threadIdx.x == 0) s_last = 0;
    __syncthreads();

    const int warp = threadIdx.x >> 5;
    const int lane = threadIdx.x & 31;
    float t0 = 0.f, t1 = 0.f;

    for (int aa = threadIdx.x; aa < A; aa += blockDim.x) {
        float acc[SVPB];
        const float bb = b1[aa];
        #pragma unroll
        for (int v = 0; v < SVPB; v++) acc[v] = bb;

        for (int d = 0; d < Dp; d += 4) {
            const float w0 = (d + 0 < D) ? W1[(size_t)(d + 0) * A + aa] : 0.f;
            const float w1 = (d + 1 < D) ? W1[(size_t)(d + 1) * A + aa] : 0.f;
            const float w2 = (d + 2 < D) ? W1[(size_t)(d + 2) * A + aa] : 0.f;
            const float w3 = (d + 3 < D) ? W1[(size_t)(d + 3) * A + aa] : 0.f;
            #pragma unroll
            for (int v = 0; v < SVPB; v++) {
                const float4 xv = *reinterpret_cast<const float4*>(&sx[v * Dp + d]);
                acc[v] = fmaf(xv.x, w0, acc[v]);
                acc[v] = fmaf(xv.y, w1, acc[v]);
                acc[v] = fmaf(xv.z, w2, acc[v]);
                acc[v] = fmaf(xv.w, w3, acc[v]);
            }
        }

        const float qa = q[aa];
        #pragma unroll
        for (int v = 0; v < SVPB; v++) {
            if (v < nv) {
                const float tv = tanhf(acc[v]) * qa;
                if (v & 1) t1 += tv; else t0 += tv;
            }
        }
    }

    #pragma unroll
    for (int off = 16; off; off >>= 1) {
        t0 += __shfl_down_sync(0xffffffffu, t0, off);
        t1 += __shfl_down_sync(0xffffffffu, t1, off);
    }
    if (lane == 0) { r0[warp] = t0; r1[warp] = t1; }
    __syncthreads();

    if (threadIdx.x == 0) {
        float s0 = r0[0] + r0[1] + r0[2] + r0[3];
        float s1 = r1[0] + r1[1] + r1[2] + r1[3];
        g_part[2 * blockIdx.x + 0] = s0;
        g_part[2 * blockIdx.x + 1] = s1;
        __threadfence();
        const unsigned int done = atomicAdd(&g_count, 1u);
        if (done == (unsigned int)(nblk - 1)) s_last = 1;
    }
    __syncthreads();

    if (s_last && warp == 0) {
        float a0 = 0.f, a1 = 0.f;
        for (int i = lane; i < nblk; i += 32) {
            a0 += g_part[2 * i + 0];
            a1 += g_part[2 * i + 1];
        }
        #pragma unroll
        for (int off = 16; off; off >>= 1) {
            a0 += __shfl_down_sync(0xffffffffu, a0, off);
            a1 += __shfl_down_sync(0xffffffffu, a1, off);
        }
        if (lane == 0) { g_score[0] = a0; g_score[1] = a1; }
    }
}

// ---------------------------------------------------------------------------
// Kernel 3: beta = softmax(score / B); out[b,d] = beta0*mean_r + beta1*mean_v
// One block per graph: no integer division, float2 I/O.
// ---------------------------------------------------------------------------
__global__ void combine_graph_kernel(float2* __restrict__ outp, int D) {
    const float invB = 1.f / (float)gridDim.x;
    const float s0 = g_score[0] * invB;
    const float s1 = g_score[1] * invB;
    const float mx = fmaxf(s0, s1);
    const float e0 = expf(s0 - mx);
    const float e1 = expf(s1 - mx);
    const float beta0 = e0 / (e0 + e1);
    const float beta1 = 1.f - beta0;

    const int b  = blockIdx.x;
    const int t  = threadIdx.x;
    const int D2 = D >> 1;
    if (t < D2) {
        const float* mrow = g_means + (size_t)b * 2 * D;
        const float2 r = reinterpret_cast<const float2*>(mrow)[t];
        const float2 v = reinterpret_cast<const float2*>(mrow + D)[t];
        outp[(size_t)b * D2 + t] = make_float2(r.x * beta0 + v.x * beta1,
                                               r.y * beta0 + v.y * beta1);
    }
}

__global__ void combine_scalar_kernel(float* __restrict__ outp, int B, int D) {
    const float invB = 1.f / (float)B;
    const float s0 = g_score[0] * invB;
    const float s1 = g_score[1] * invB;
    const float mx = fmaxf(s0, s1);
    const float e0 = expf(s0 - mx);
    const float e1 = expf(s1 - mx);
    const float beta0 = e0 / (e0 + e1);
    const float beta1 = 1.f - beta0;

    const int idx = blockIdx.x * blockDim.x + threadIdx.x;
    const int tot = B * D;
    if (idx < tot) {
        const int b = idx / D;
        const int d = idx - b * D;
        const float* mr = g_means + (size_t)b * 2 * D;
        outp[idx] = mr[d] * beta0 + mr[D + d] * beta1;
    }
}

// ---------------------------------------------------------------------------
extern "C" void kernel_launch(void* const* d_in, const int* in_sizes, int n_in,
                              void* d_out, int out_size) {
    const float* x   = (const float*)d_in[0];   // out [N, D] fp32
    const int*   z   = (const int*)d_in[1];     // z   [N] int32/int64
    const int*   bat = (const int*)d_in[2];     // batch [N] sorted int32/int64
    const float* W1  = (const float*)d_in[3];   // [D, A]
    const float* b1  = (const float*)d_in[4];   // [A]
    const float* q   = (const float*)d_in[5];   // [A, 1]

    const int N = in_sizes[1];
    const int D = in_sizes[0] / N;
    const int A = in_sizes[4];
    const int B = out_size / D;

    detect_kernel<<<1, 32>>>(bat, N);                        // launch 1
    bounds_kernel<<<(N + 255) / 256, 256>>>(bat, N, B);      // launch 2
    mask_kernel<<<(N / 4 + 256) / 256, 256>>>(z, N);         // launch 3

    const int PQ = D >> 1;                                   // float4s per pair
    const bool fast = ((D & 1) == 0) && (N <= MAXN) && (D <= MAXD) &&
                      (PQ <= 96) && (B <= MAXB);
    if (fast) {                                              // launch 4 (profiled)
        if (PQ == 75) seg_mean_part<75><<<B * NSPLIT, 96>>>(x, D, PQ);
        else          seg_mean_part<0><<<B * NSPLIT, 96>>>(x, D, PQ);
        finalize_kernel<<<B, ((PQ + 31) / 32) * 32>>>(D);    // launch 5
    } else {
        int tpb = ((D + 31) / 32) * 32;
        if (tpb > 1024) tpb = 1024;
        seg_mean_scalar_kernel<<<B, tpb>>>(x, z, D);
    }

    const int Dp = (D + 3) & ~3;
    const int nblk2 = (B + SGPB - 1) / SGPB;
    const size_t shmem = (size_t)SVPB * Dp * sizeof(float);
    score_kernel<<<nblk2, 128, shmem>>>(W1, b1, q, D, Dp, A, B, nblk2);

    if ((D & 1) == 0) {
        const int D2 = D >> 1;
        int tpb = ((D2 + 31) / 32) * 32;
        if (tpb > 1024) tpb = 1024;
        combine_graph_kernel<<<B, tpb>>>((float2*)d_out, D);
    } else {
        const int tot = B * D;
        combine_scalar_kernel<<<(tot + 255) / 256, 256>>>((float*)d_out, B, D);
    }
}

// round 10
// speedup vs baseline: 1.2859x; 1.2313x over previous
#include <cuda_runtime.h>

// ---------------------------------------------------------------------------
// RealVirtualAttention:
//   1) masked segment-mean over sorted batch (real vs virtual nodes) -> [B,2,D]
//   2) HAN semantic attention: score_m = sum_b q^T tanh(W1^T x_{b,m} + b1)
//      beta = softmax(score / B)
//   3) out[b] = beta0 * mean_real[b] + beta1 * mean_virtual[b]
// ---------------------------------------------------------------------------

#define VIRTUAL_Z 100
#define MAXB 8192
#define MAXD 256
#define MAXN (1 << 22)             // mask capacity: 4M rows (16 MB)
#define SGPB 4                     // graphs per block in score kernel
#define SVPB (2*SGPB)              // vectors per block (8)

typedef unsigned long long u64;

__device__ float g_means[(size_t)MAXB * 2 * MAXD];   // [B][2][D] means
__device__ float g_part[(MAXB / SGPB) * 2 + 2];      // per-block partial scores
__device__ float g_score[2];
__device__ int   g_is64;
__device__ int   g_bounds[MAXB + 1];                 // row range per graph
__device__ unsigned int g_count;                     // score-block completion ctr
__device__ float g_maskf[MAXN];                      // 1.0 = real, 0.0 = virtual

// ---- packed f32x2 helpers --------------------------------------------------
__device__ __forceinline__ u64 ld64cs(const float* p) {
    u64 v;
    asm volatile("ld.global.cs.b64 %0, [%1];" : "=l"(v) : "l"(p));
    return v;
}
__device__ __forceinline__ void ld128cs(const float* p, u64& a, u64& b) {
    asm volatile("ld.global.cs.v2.b64 {%0, %1}, [%2];"
                 : "=l"(a), "=l"(b) : "l"(p));
}
__device__ __forceinline__ void add2(u64& a, u64 b) {
    asm("add.rn.f32x2 %0, %1, %2;" : "=l"(a) : "l"(a), "l"(b));
}
__device__ __forceinline__ void fma2(u64& a, u64 m, u64 v) {
    asm("fma.rn.f32x2 %0, %1, %2, %3;" : "=l"(a) : "l"(m), "l"(v), "l"(a));
}
__device__ __forceinline__ u64 dup2(float m) {
    u64 r;
    asm("mov.b64 %0, {%1, %1};" : "=l"(r) : "f"(m));
    return r;
}
__device__ __forceinline__ float2 unpk(u64 v) {
    float2 r;
    asm("mov.b64 {%0, %1}, %2;" : "=f"(r.x), "=f"(r.y) : "l"(v));
    return r;
}

// ---------------------------------------------------------------------------
// Detect int32 vs int64 (jax silently downcasts int64 -> int32 when x64 is
// disabled): viewing as int32, odd slots near the end are 0 iff int64.
// Also resets g_count for the score kernel's last-block election.
// ---------------------------------------------------------------------------
__global__ void detect_kernel(const int* __restrict__ bat32, int N) {
    if (threadIdx.x == 0) {
        int is64 = 1;
        int idx = N - 1;
        if ((idx & 1) == 0) idx--;
        for (int k = 0; k < 8 && idx >= 1; k++, idx -= 2) {
            if (bat32[idx] != 0) { is64 = 0; break; }
        }
        g_is64 = is64;
        g_count = 0u;
    }
}

// ---------------------------------------------------------------------------
// Fused bounds+mask kernel (one pass over batch and z):
//   g_bounds[b] = first row index with batch >= b
//   g_maskf[i]  = (z[i] != VIRTUAL_Z) ? 1.f : 0.f
// ---------------------------------------------------------------------------
__global__ void bounds_mask_kernel(const int* __restrict__ bat32,
                                   const int* __restrict__ z32,
                                   int N, int B) {
    const int s = g_is64;
    const int i = blockIdx.x * blockDim.x + threadIdx.x;
    if (i >= N) return;

    g_maskf[i] = (z32[(size_t)i << s] != VIRTUAL_Z) ? 1.f : 0.f;

    const int cur  = bat32[(size_t)i << s];
    const int prev = (i == 0) ? -1 : bat32[(size_t)(i - 1) << s];
    for (int b = prev + 1; b <= cur; b++) g_bounds[b] = i;
    if (i == N - 1) {
        for (int b = cur + 1; b <= B; b++) g_bounds[b] = N;
    }
}

// ---------------------------------------------------------------------------
// Kernel 1 (hot, R7-proven): row-PAIR float4 streaming. Two consecutive rows
// = D/2 float4s; for even global row index the pair block is 16B aligned.
// Thread t owns float4 #t of each pair block: 16-row (8-pair) chunks give
// 128 B in flight per thread via LDG.128. Packed f32x2 masked accumulation;
// each packed half uses mask m0 (first row of pair) or m1 (second), selected
// by a per-thread constant. A once-per-block SMEM transpose undoes the
// feature permutation; prologue/tail rows use the scalar 2-float path.
// sv = st - sr; counts from mask sums.
// ---------------------------------------------------------------------------
template <int PQS>   // PQ = D/2 (float4s per pair block); 0 = runtime
__global__ void seg_mean_pair(const float* __restrict__ x, int D, int PQrt) {
    const int PQ = (PQS > 0) ? PQS : PQrt;
    const int b = blockIdx.x;
    const int start = g_bounds[b];
    const int end   = g_bounds[b + 1];
    const int t   = threadIdx.x;
    const bool act = (t < PQ);
    const int  tc  = act ? t : (PQ - 1);        // clamp: no divergence

    const bool lowR0  = (4 * tc + 1 < D);       // low packed half in first row?
    const bool highR0 = (4 * tc + 3 < D);       // high packed half in first row?

    u64 stL = 0ull, srL = 0ull, stH = 0ull, srH = 0ull;  // pair-loop accs
    u64 stP = 0ull, srP = 0ull;                 // scalar-row accs (feat 2tc,2tc+1)
    float crf = 0.f;

    int i = start;
    // Scalar prologue: align i to a multiple of 4.
    for (; i < end && (i & 3); i++) {
        const float m = g_maskf[i];
        const u64 v = ld64cs(x + (size_t)i * D + 2 * tc);
        add2(stP, v); fma2(srP, dup2(m), v); crf += m;
    }

    const float* xp = x + (size_t)i * D + 4 * tc;
    // Main: 16 rows = 8 pairs per iteration.
    for (; i + 16 <= end; i += 16, xp += (size_t)16 * D) {
        float4 mq[4];
        #pragma unroll
        for (int j = 0; j < 4; j++)
            mq[j] = *reinterpret_cast<const float4*>(&g_maskf[i + 4 * j]);
        u64 vl[8], vh[8];
        #pragma unroll
        for (int k = 0; k < 8; k++)
            ld128cs(xp + (size_t)2 * k * D, vl[k], vh[k]);

        #pragma unroll
        for (int k = 0; k < 8; k++) {
            const float4 mk = mq[k >> 1];
            const float m0 = (k & 1) ? mk.z : mk.x;
            const float m1 = (k & 1) ? mk.w : mk.y;
            const u64 d0 = dup2(m0), d1 = dup2(m1);
            add2(stL, vl[k]); fma2(srL, lowR0  ? d0 : d1, vl[k]);
            add2(stH, vh[k]); fma2(srH, highR0 ? d0 : d1, vh[k]);
        }
        crf += mq[0].x + mq[0].y + mq[0].z + mq[0].w
             + mq[1].x + mq[1].y + mq[1].z + mq[1].w
             + mq[2].x + mq[2].y + mq[2].z + mq[2].w
             + mq[3].x + mq[3].y + mq[3].z + mq[3].w;
    }
    // Tail pairs (i still even).
    for (; i + 2 <= end; i += 2, xp += (size_t)2 * D) {
        const float m0 = g_maskf[i];
        const float m1 = g_maskf[i + 1];
        u64 a, c;
        ld128cs(xp, a, c);
        const u64 d0 = dup2(m0), d1 = dup2(m1);
        add2(stL, a); fma2(srL, lowR0  ? d0 : d1, a);
        add2(stH, c); fma2(srH, highR0 ? d0 : d1, c);
        crf += m0 + m1;
    }
    // Final odd row.
    for (; i < end; i++) {
        const float m = g_maskf[i];
        const u64 v = ld64cs(x + (size_t)i * D + 2 * tc);
        add2(stP, v); fma2(srP, dup2(m), v); crf += m;
    }

    // Undo the pair-block feature permutation via SMEM.
    __shared__ float sst[2 * MAXD], ssr[2 * MAXD];
    if (act) {
        const float2 l = unpk(stL), h = unpk(stH);
        sst[4 * t + 0] = l.x; sst[4 * t + 1] = l.y;
        sst[4 * t + 2] = h.x; sst[4 * t + 3] = h.y;
        const float2 rl = unpk(srL), rh = unpk(srH);
        ssr[4 * t + 0] = rl.x; ssr[4 * t + 1] = rl.y;
        ssr[4 * t + 2] = rh.x; ssr[4 * t + 3] = rh.y;
    }
    __syncthreads();

    if (act) {
        const float2 pst = unpk(stP), psr = unpk(srP);
        const int f0 = 2 * t, f1 = 2 * t + 1;
        const float st0 = sst[f0] + sst[f0 + D] + pst.x;
        const float st1 = sst[f1] + sst[f1 + D] + pst.y;
        const float sr0 = ssr[f0] + ssr[f0 + D] + psr.x;
        const float sr1 = ssr[f1] + ssr[f1 + D] + psr.y;
        const float cr = crf;
        const float cv = (float)(end - start) - cr;
        const float ir = 1.f / fmaxf(cr, 1.f);
        const float iv = 1.f / fmaxf(cv, 1.f);
        float* mr = g_means + (size_t)b * 2 * D;
        reinterpret_cast<float2*>(mr)[t]     = make_float2(sr0 * ir, sr1 * ir);
        reinterpret_cast<float2*>(mr + D)[t] = make_float2((st0 - sr0) * iv,
                                                           (st1 - sr1) * iv);
    }
}

// Scalar fallback for odd D or PQ > 96 (not hit for this problem's shapes).
__global__ void seg_mean_scalar_kernel(const float* __restrict__ x,
                                       const int*   __restrict__ z32,
                                       int D) {
    const int b = blockIdx.x;
    const int s = g_is64;
    const int start = g_bounds[b];
    const int end   = g_bounds[b + 1];
    const int t = threadIdx.x;

    float srs = 0.f, svs = 0.f;
    int cr = 0, cv = 0;
    for (int i = start; i < end; i++) {
        const int zz = z32[(size_t)i << s];
        float v = (t < D) ? x[(size_t)i * D + t] : 0.f;
        if (zz != VIRTUAL_Z) { srs += v; cr++; } else { svs += v; cv++; }
    }
    if (t < D) {
        float* mr = g_means + (size_t)b * 2 * D;
        mr[t]     = srs / (float)max(cr, 1);
        mr[D + t] = svs / (float)max(cv, 1);
    }
}

// ---------------------------------------------------------------------------
// Kernel 2: semantic attention scores (measured-best config).
// Block = 128 threads; each thread owns one aa column. SGPB=4 graphs
// (SVPB=8 vectors) per block. W1 stays L1/L2-resident. Last block
// (atomic-counter elect) does the fixed-order final reduction.
// ---------------------------------------------------------------------------
__global__ void score_kernel(const float* __restrict__ W1,
                             const float* __restrict__ b1,
                             const float* __restrict__ q,
                             int D, int Dp, int A, int B, int nblk) {
    extern __shared__ float sx[];   // [SVPB][Dp]
    __shared__ float r0[4], r1[4];
    __shared__ int   s_last;

    const int b0 = blockIdx.x * SGPB;
    const int nv = min(SVPB, 2 * (B - b0));   // valid vectors in this block

    for (int i = threadIdx.x; i < SVPB * Dp; i += blockDim.x) {
        const int v = i / Dp;
        const int d = i - v * Dp;
        float val = 0.f;
        if (v < nv && d < D) val = g_means[((size_t)b0 * 2 + v) * D + d];
        sx[i] = val;
    }
    if (threadIdx.x == 0) s_last = 0;
    __syncthreads();

    const int warp = threadIdx.x >> 5;
    const int lane = threadIdx.x & 31;
    float t0 = 0.f, t1 = 0.f;

    for (int aa = threadIdx.x; aa < A; aa += blockDim.x) {
        float acc[SVPB];
        const float bb = b1[aa];
        const float qa = q[aa];
        #pragma unroll
        for (int v = 0; v < SVPB; v++) acc[v] = bb;

        for (int d = 0; d < Dp; d += 4) {
            const float w0 = (d + 0 < D) ? W1[(size_t)(d + 0) * A + aa] : 0.f;
            const float w1 = (d + 1 < D) ? W1[(size_t)(d + 1) * A + aa] : 0.f;
            const float w2 = (d + 2 < D) ? W1[(size_t)(d + 2) * A + aa] : 0.f;
            const float w3 = (d + 3 < D) ? W1[(size_t)(d + 3) * A + aa] : 0.f;
            #pragma unroll
            for (int v = 0; v < SVPB; v++) {
                const float4 xv = *reinterpret_cast<const float4*>(&sx[v * Dp + d]);
                acc[v] = fmaf(xv.x, w0, acc[v]);
                acc[v] = fmaf(xv.y, w1, acc[v]);
                acc[v] = fmaf(xv.z, w2, acc[v]);
                acc[v] = fmaf(xv.w, w3, acc[v]);
            }
        }

        #pragma unroll
        for (int v = 0; v < SVPB; v++) {
            if (v < nv) {
                const float tv = tanhf(acc[v]) * qa;
                if (v & 1) t1 += tv; else t0 += tv;
            }
        }
    }

    #pragma unroll
    for (int off = 16; off; off >>= 1) {
        t0 += __shfl_down_sync(0xffffffffu, t0, off);
        t1 += __shfl_down_sync(0xffffffffu, t1, off);
    }
    if (lane == 0) { r0[warp] = t0; r1[warp] = t1; }
    __syncthreads();

    if (threadIdx.x == 0) {
        float s0 = r0[0] + r0[1] + r0[2] + r0[3];
        float s1 = r1[0] + r1[1] + r1[2] + r1[3];
        g_part[2 * blockIdx.x + 0] = s0;
        g_part[2 * blockIdx.x + 1] = s1;
        __threadfence();
        const unsigned int done = atomicAdd(&g_count, 1u);
        if (done == (unsigned int)(nblk - 1)) s_last = 1;
    }
    __syncthreads();

    if (s_last && warp == 0) {
        float a0 = 0.f, a1 = 0.f;
        for (int i = lane; i < nblk; i += 32) {
            a0 += g_part[2 * i + 0];
            a1 += g_part[2 * i + 1];
        }
        #pragma unroll
        for (int off = 16; off; off >>= 1) {
            a0 += __shfl_down_sync(0xffffffffu, a0, off);
            a1 += __shfl_down_sync(0xffffffffu, a1, off);
        }
        if (lane == 0) { g_score[0] = a0; g_score[1] = a1; }
    }
}

// ---------------------------------------------------------------------------
// Kernel 3: beta = softmax(score / B); out[b,d] = beta0*mean_r + beta1*mean_v
// One block per graph: no integer division, float2 I/O.
// ---------------------------------------------------------------------------
__global__ void combine_graph_kernel(float2* __restrict__ outp, int D) {
    const float invB = 1.f / (float)gridDim.x;
    const float s0 = g_score[0] * invB;
    const float s1 = g_score[1] * invB;
    const float mx = fmaxf(s0, s1);
    const float e0 = expf(s0 - mx);
    const float e1 = expf(s1 - mx);
    const float beta0 = e0 / (e0 + e1);
    const float beta1 = 1.f - beta0;

    const int b  = blockIdx.x;
    const int t  = threadIdx.x;
    const int D2 = D >> 1;
    if (t < D2) {
        const float* mrow = g_means + (size_t)b * 2 * D;
        const float2 r = reinterpret_cast<const float2*>(mrow)[t];
        const float2 v = reinterpret_cast<const float2*>(mrow + D)[t];
        outp[(size_t)b * D2 + t] = make_float2(r.x * beta0 + v.x * beta1,
                                               r.y * beta0 + v.y * beta1);
    }
}

__global__ void combine_scalar_kernel(float* __restrict__ outp, int B, int D) {
    const float invB = 1.f / (float)B;
    const float s0 = g_score[0] * invB;
    const float s1 = g_score[1] * invB;
    const float mx = fmaxf(s0, s1);
    const float e0 = expf(s0 - mx);
    const float e1 = expf(s1 - mx);
    const float beta0 = e0 / (e0 + e1);
    const float beta1 = 1.f - beta0;

    const int idx = blockIdx.x * blockDim.x + threadIdx.x;
    const int tot = B * D;
    if (idx < tot) {
        const int b = idx / D;
        const int d = idx - b * D;
        const float* mr = g_means + (size_t)b * 2 * D;
        outp[idx] = mr[d] * beta0 + mr[D + d] * beta1;
    }
}

// ---------------------------------------------------------------------------
extern "C" void kernel_launch(void* const* d_in, const int* in_sizes, int n_in,
                              void* d_out, int out_size) {
    const float* x   = (const float*)d_in[0];   // out [N, D] fp32
    const int*   z   = (const int*)d_in[1];     // z   [N] int32/int64
    const int*   bat = (const int*)d_in[2];     // batch [N] sorted int32/int64
    const float* W1  = (const float*)d_in[3];   // [D, A]
    const float* b1  = (const float*)d_in[4];   // [A]
    const float* q   = (const float*)d_in[5];   // [A, 1]

    const int N = in_sizes[1];
    const int D = in_sizes[0] / N;
    const int A = in_sizes[4];
    const int B = out_size / D;

    detect_kernel<<<1, 32>>>(bat, N);                            // launch 1
    bounds_mask_kernel<<<(N + 255) / 256, 256>>>(bat, z, N, B);  // launch 2

    const int PQ = D >> 1;                                   // float4s per pair
    const bool fast = ((D & 1) == 0) && (N <= MAXN) && (D <= MAXD) && (PQ <= 96);
    if (fast) {                                              // launch 3
        if (PQ == 75) seg_mean_pair<75><<<B, 96>>>(x, D, PQ);
        else          seg_mean_pair<0><<<B, ((PQ + 31) / 32) * 32>>>(x, D, PQ);
    } else {
        int tpb = ((D + 31) / 32) * 32;
        if (tpb > 1024) tpb = 1024;
        seg_mean_scalar_kernel<<<B, tpb>>>(x, z, D);
    }

    const int Dp = (D + 3) & ~3;
    const int nblk2 = (B + SGPB - 1) / SGPB;
    const size_t shmem = (size_t)SVPB * Dp * sizeof(float);
    score_kernel<<<nblk2, 128, shmem>>>(W1, b1, q, D, Dp, A, B, nblk2);  // 4 (profiled)

    if ((D & 1) == 0) {                                      // launch 5
        const int D2 = D >> 1;
        int tpb = ((D2 + 31) / 32) * 32;
        if (tpb > 1024) tpb = 1024;
        combine_graph_kernel<<<B, tpb>>>((float2*)d_out, D);
    } else {
        const int tot = B * D;
        combine_scalar_kernel<<<(tot + 255) / 256, 256>>>((float*)d_out, B, D);
    }
}

// round 11
// speedup vs baseline: 1.3093x; 1.0182x over previous
#include <cuda_runtime.h>

// ---------------------------------------------------------------------------
// RealVirtualAttention:
//   1) masked segment-mean over sorted batch (real vs virtual nodes) -> [B,2,D]
//   2) HAN semantic attention: score_m = sum_b q^T tanh(W1^T x_{b,m} + b1)
//      beta = softmax(score / B)
//   3) out[b] = beta0 * mean_real[b] + beta1 * mean_virtual[b]
// ---------------------------------------------------------------------------

#define VIRTUAL_Z 100
#define MAXB 8192
#define MAXD 256
#define MAXA 512
#define MAXN (1 << 22)             // mask capacity: 4M rows (16 MB)
#define SGPB 4                     // graphs per block in score kernel
#define SVPB (2*SGPB)              // vectors per block (8)

typedef unsigned long long u64;

__device__ float g_means[(size_t)MAXB * 2 * MAXD];   // [B][2][D] means
__device__ float g_w1t[(size_t)MAXA * MAXD];         // W1 transposed [A][Dp]
__device__ float g_part[(MAXB / SGPB) * 2 + 2];      // per-block partial scores
__device__ float g_score[2];
__device__ int   g_is64;
__device__ int   g_bounds[MAXB + 1];                 // row range per graph
__device__ unsigned int g_count;                     // score-block completion ctr
__device__ float g_maskf[MAXN];                      // 1.0 = real, 0.0 = virtual

// ---- packed f32x2 / misc helpers -------------------------------------------
__device__ __forceinline__ u64 ld64cs(const float* p) {
    u64 v;
    asm volatile("ld.global.cs.b64 %0, [%1];" : "=l"(v) : "l"(p));
    return v;
}
__device__ __forceinline__ void ld128cs(const float* p, u64& a, u64& b) {
    asm volatile("ld.global.cs.v2.b64 {%0, %1}, [%2];"
                 : "=l"(a), "=l"(b) : "l"(p));
}
__device__ __forceinline__ void add2(u64& a, u64 b) {
    asm("add.rn.f32x2 %0, %1, %2;" : "=l"(a) : "l"(a), "l"(b));
}
__device__ __forceinline__ void fma2(u64& a, u64 m, u64 v) {
    asm("fma.rn.f32x2 %0, %1, %2, %3;" : "=l"(a) : "l"(m), "l"(v), "l"(a));
}
__device__ __forceinline__ u64 dup2(float m) {
    u64 r;
    asm("mov.b64 %0, {%1, %1};" : "=l"(r) : "f"(m));
    return r;
}
__device__ __forceinline__ float2 unpk(u64 v) {
    float2 r;
    asm("mov.b64 {%0, %1}, %2;" : "=f"(r.x), "=f"(r.y) : "l"(v));
    return r;
}
__device__ __forceinline__ float tanh_fast(float x) {
    float y;
    asm("tanh.approx.f32 %0, %1;" : "=f"(y) : "f"(x));
    return y;
}

// ---------------------------------------------------------------------------
// Launch 1 (fused): dtype detect + W1 transpose.
// Detect int32 vs int64 (jax silently downcasts int64 -> int32 when x64 is
// disabled): viewing as int32, odd slots near the end are 0 iff int64.
// Transpose: g_w1t[aa*Dp + d] = W1[d*A + aa], zero-padded for d in [D, Dp)
// so the score kernel needs no bounds checks and loads W1 rows as float4.
// ---------------------------------------------------------------------------
__global__ void detect_transpose_kernel(const int* __restrict__ bat32, int N,
                                        const float* __restrict__ W1,
                                        int D, int Dp, int A) {
    if (blockIdx.x == 0 && threadIdx.x == 0) {
        int is64 = 1;
        int idx = N - 1;
        if ((idx & 1) == 0) idx--;
        for (int k = 0; k < 8 && idx >= 1; k++, idx -= 2) {
            if (bat32[idx] != 0) { is64 = 0; break; }
        }
        g_is64 = is64;
        g_count = 0u;
    }
    const int total = A * Dp;
    for (int i = blockIdx.x * blockDim.x + threadIdx.x; i < total;
         i += gridDim.x * blockDim.x) {
        const int aa = i / Dp;
        const int d  = i - aa * Dp;
        g_w1t[i] = (d < D) ? W1[(size_t)d * A + aa] : 0.f;
    }
}

// ---------------------------------------------------------------------------
// Launch 2 (fused): bounds + mask, one pass over batch and z:
//   g_bounds[b] = first row index with batch >= b
//   g_maskf[i]  = (z[i] != VIRTUAL_Z) ? 1.f : 0.f
// ---------------------------------------------------------------------------
__global__ void bounds_mask_kernel(const int* __restrict__ bat32,
                                   const int* __restrict__ z32,
                                   int N, int B) {
    const int s = g_is64;
    const int i = blockIdx.x * blockDim.x + threadIdx.x;
    if (i >= N) return;

    g_maskf[i] = (z32[(size_t)i << s] != VIRTUAL_Z) ? 1.f : 0.f;

    const int cur  = bat32[(size_t)i << s];
    const int prev = (i == 0) ? -1 : bat32[(size_t)(i - 1) << s];
    for (int b = prev + 1; b <= cur; b++) g_bounds[b] = i;
    if (i == N - 1) {
        for (int b = cur + 1; b <= B; b++) g_bounds[b] = N;
    }
}

// ---------------------------------------------------------------------------
// Kernel 1 (hot, R7-proven, FROZEN): row-PAIR float4 streaming. Two rows =
// D/2 float4s; pair blocks are 16B aligned at even row indices. Thread t
// owns float4 #t: 16-row (8-pair) chunks give 8 LDG.128 in flight (128 B)
// per thread. Packed f32x2 masked accumulation; SMEM transpose undoes the
// feature permutation; scalar prologue/tail. sv = st - sr.
// ---------------------------------------------------------------------------
template <int PQS>   // PQ = D/2 (float4s per pair block); 0 = runtime
__global__ void seg_mean_pair(const float* __restrict__ x, int D, int PQrt) {
    const int PQ = (PQS > 0) ? PQS : PQrt;
    const int b = blockIdx.x;
    const int start = g_bounds[b];
    const int end   = g_bounds[b + 1];
    const int t   = threadIdx.x;
    const bool act = (t < PQ);
    const int  tc  = act ? t : (PQ - 1);        // clamp: no divergence

    const bool lowR0  = (4 * tc + 1 < D);       // low packed half in first row?
    const bool highR0 = (4 * tc + 3 < D);       // high packed half in first row?

    u64 stL = 0ull, srL = 0ull, stH = 0ull, srH = 0ull;  // pair-loop accs
    u64 stP = 0ull, srP = 0ull;                 // scalar-row accs (feat 2tc,2tc+1)
    float crf = 0.f;

    int i = start;
    // Scalar prologue: align i to a multiple of 4.
    for (; i < end && (i & 3); i++) {
        const float m = g_maskf[i];
        const u64 v = ld64cs(x + (size_t)i * D + 2 * tc);
        add2(stP, v); fma2(srP, dup2(m), v); crf += m;
    }

    const float* xp = x + (size_t)i * D + 4 * tc;
    // Main: 16 rows = 8 pairs per iteration.
    for (; i + 16 <= end; i += 16, xp += (size_t)16 * D) {
        float4 mq[4];
        #pragma unroll
        for (int j = 0; j < 4; j++)
            mq[j] = *reinterpret_cast<const float4*>(&g_maskf[i + 4 * j]);
        u64 vl[8], vh[8];
        #pragma unroll
        for (int k = 0; k < 8; k++)
            ld128cs(xp + (size_t)2 * k * D, vl[k], vh[k]);

        #pragma unroll
        for (int k = 0; k < 8; k++) {
            const float4 mk = mq[k >> 1];
            const float m0 = (k & 1) ? mk.z : mk.x;
            const float m1 = (k & 1) ? mk.w : mk.y;
            const u64 d0 = dup2(m0), d1 = dup2(m1);
            add2(stL, vl[k]); fma2(srL, lowR0  ? d0 : d1, vl[k]);
            add2(stH, vh[k]); fma2(srH, highR0 ? d0 : d1, vh[k]);
        }
        crf += mq[0].x + mq[0].y + mq[0].z + mq[0].w
             + mq[1].x + mq[1].y + mq[1].z + mq[1].w
             + mq[2].x + mq[2].y + mq[2].z + mq[2].w
             + mq[3].x + mq[3].y + mq[3].z + mq[3].w;
    }
    // Tail pairs (i still even).
    for (; i + 2 <= end; i += 2, xp += (size_t)2 * D) {
        const float m0 = g_maskf[i];
        const float m1 = g_maskf[i + 1];
        u64 a, c;
        ld128cs(xp, a, c);
        const u64 d0 = dup2(m0), d1 = dup2(m1);
        add2(stL, a); fma2(srL, lowR0  ? d0 : d1, a);
        add2(stH, c); fma2(srH, highR0 ? d0 : d1, c);
        crf += m0 + m1;
    }
    // Final odd row.
    for (; i < end; i++) {
        const float m = g_maskf[i];
        const u64 v = ld64cs(x + (size_t)i * D + 2 * tc);
        add2(stP, v); fma2(srP, dup2(m), v); crf += m;
    }

    // Undo the pair-block feature permutation via SMEM.
    __shared__ float sst[2 * MAXD], ssr[2 * MAXD];
    if (act) {
        const float2 l = unpk(stL), h = unpk(stH);
        sst[4 * t + 0] = l.x; sst[4 * t + 1] = l.y;
        sst[4 * t + 2] = h.x; sst[4 * t + 3] = h.y;
        const float2 rl = unpk(srL), rh = unpk(srH);
        ssr[4 * t + 0] = rl.x; ssr[4 * t + 1] = rl.y;
        ssr[4 * t + 2] = rh.x; ssr[4 * t + 3] = rh.y;
    }
    __syncthreads();

    if (act) {
        const float2 pst = unpk(stP), psr = unpk(srP);
        const int f0 = 2 * t, f1 = 2 * t + 1;
        const float st0 = sst[f0] + sst[f0 + D] + pst.x;
        const float st1 = sst[f1] + sst[f1 + D] + pst.y;
        const float sr0 = ssr[f0] + ssr[f0 + D] + psr.x;
        const float sr1 = ssr[f1] + ssr[f1 + D] + psr.y;
        const float cr = crf;
        const float cv = (float)(end - start) - cr;
        const float ir = 1.f / fmaxf(cr, 1.f);
        const float iv = 1.f / fmaxf(cv, 1.f);
        float* mr = g_means + (size_t)b * 2 * D;
        reinterpret_cast<float2*>(mr)[t]     = make_float2(sr0 * ir, sr1 * ir);
        reinterpret_cast<float2*>(mr + D)[t] = make_float2((st0 - sr0) * iv,
                                                           (st1 - sr1) * iv);
    }
}

// Scalar fallback for odd D or PQ > 96 (not hit for this problem's shapes).
__global__ void seg_mean_scalar_kernel(const float* __restrict__ x,
                                       const int*   __restrict__ z32,
                                       int D) {
    const int b = blockIdx.x;
    const int s = g_is64;
    const int start = g_bounds[b];
    const int end   = g_bounds[b + 1];
    const int t = threadIdx.x;

    float srs = 0.f, svs = 0.f;
    int cr = 0, cv = 0;
    for (int i = start; i < end; i++) {
        const int zz = z32[(size_t)i << s];
        float v = (t < D) ? x[(size_t)i * D + t] : 0.f;
        if (zz != VIRTUAL_Z) { srs += v; cr++; } else { svs += v; cv++; }
    }
    if (t < D) {
        float* mr = g_means + (size_t)b * 2 * D;
        mr[t]     = srs / (float)max(cr, 1);
        mr[D + t] = svs / (float)max(cv, 1);
    }
}

// ---------------------------------------------------------------------------
// Kernel 2: semantic attention scores. Same block shape as the measured-best
// config (128 threads, SGPB=4), but: W1 is read from the pre-transposed,
// zero-padded g_w1t via a single aligned LDG.128 per 4-d chunk (no strided
// scalar loads, no bounds predicates), and tanh uses tanh.approx.f32
// (1 MUFU op instead of a ~25-instruction libm sequence; 1M evaluations).
// Last block (atomic-counter elect) does the fixed-order final reduction.
// ---------------------------------------------------------------------------
__global__ void score_kernel(const float* __restrict__ b1,
                             const float* __restrict__ q,
                             int D, int Dp, int A, int B, int nblk) {
    extern __shared__ float sx[];   // [SVPB][Dp]
    __shared__ float r0[4], r1[4];
    __shared__ int   s_last;

    const int b0 = blockIdx.x * SGPB;
    const int nv = min(SVPB, 2 * (B - b0));   // valid vectors in this block

    for (int i = threadIdx.x; i < SVPB * Dp; i += blockDim.x) {
        const int v = i / Dp;
        const int d = i - v * Dp;
        float val = 0.f;
        if (v < nv && d < D) val = g_means[((size_t)b0 * 2 + v) * D + d];
        sx[i] = val;
    }
    if (threadIdx.x == 0) s_last = 0;
    __syncthreads();

    const int warp = threadIdx.x >> 5;
    const int lane = threadIdx.x & 31;
    float t0 = 0.f, t1 = 0.f;

    for (int aa = threadIdx.x; aa < A; aa += blockDim.x) {
        float acc[SVPB];
        const float bb = b1[aa];
        const float qa = q[aa];
        #pragma unroll
        for (int v = 0; v < SVPB; v++) acc[v] = bb;

        const float* wrow = g_w1t + (size_t)aa * Dp;
        for (int d = 0; d < Dp; d += 4) {
            const float4 w = *reinterpret_cast<const float4*>(&wrow[d]);
            #pragma unroll
            for (int v = 0; v < SVPB; v++) {
                const float4 xv = *reinterpret_cast<const float4*>(&sx[v * Dp + d]);
                acc[v] = fmaf(xv.x, w.x, acc[v]);
                acc[v] = fmaf(xv.y, w.y, acc[v]);
                acc[v] = fmaf(xv.z, w.z, acc[v]);
                acc[v] = fmaf(xv.w, w.w, acc[v]);
            }
        }

        #pragma unroll
        for (int v = 0; v < SVPB; v++) {
            if (v < nv) {
                const float tv = tanh_fast(acc[v]) * qa;
                if (v & 1) t1 += tv; else t0 += tv;
            }
        }
    }

    #pragma unroll
    for (int off = 16; off; off >>= 1) {
        t0 += __shfl_down_sync(0xffffffffu, t0, off);
        t1 += __shfl_down_sync(0xffffffffu, t1, off);
    }
    if (lane == 0) { r0[warp] = t0; r1[warp] = t1; }
    __syncthreads();

    if (threadIdx.x == 0) {
        float s0 = r0[0] + r0[1] + r0[2] + r0[3];
        float s1 = r1[0] + r1[1] + r1[2] + r1[3];
        g_part[2 * blockIdx.x + 0] = s0;
        g_part[2 * blockIdx.x + 1] = s1;
        __threadfence();
        const unsigned int done = atomicAdd(&g_count, 1u);
        if (done == (unsigned int)(nblk - 1)) s_last = 1;
    }
    __syncthreads();

    if (s_last && warp == 0) {
        float a0 = 0.f, a1 = 0.f;
        for (int i = lane; i < nblk; i += 32) {
            a0 += g_part[2 * i + 0];
            a1 += g_part[2 * i + 1];
        }
        #pragma unroll
        for (int off = 16; off; off >>= 1) {
            a0 += __shfl_down_sync(0xffffffffu, a0, off);
            a1 += __shfl_down_sync(0xffffffffu, a1, off);
        }
        if (lane == 0) { g_score[0] = a0; g_score[1] = a1; }
    }
}

// ---------------------------------------------------------------------------
// Kernel 3: beta = softmax(score / B); out[b,d] = beta0*mean_r + beta1*mean_v
// One block per graph: no integer division, float2 I/O.
// ---------------------------------------------------------------------------
__global__ void combine_graph_kernel(float2* __restrict__ outp, int D) {
    const float invB = 1.f / (float)gridDim.x;
    const float s0 = g_score[0] * invB;
    const float s1 = g_score[1] * invB;
    const float mx = fmaxf(s0, s1);
    const float e0 = expf(s0 - mx);
    const float e1 = expf(s1 - mx);
    const float beta0 = e0 / (e0 + e1);
    const float beta1 = 1.f - beta0;

    const int b  = blockIdx.x;
    const int t  = threadIdx.x;
    const int D2 = D >> 1;
    if (t < D2) {
        const float* mrow = g_means + (size_t)b * 2 * D;
        const float2 r = reinterpret_cast<const float2*>(mrow)[t];
        const float2 v = reinterpret_cast<const float2*>(mrow + D)[t];
        outp[(size_t)b * D2 + t] = make_float2(r.x * beta0 + v.x * beta1,
                                               r.y * beta0 + v.y * beta1);
    }
}

__global__ void combine_scalar_kernel(float* __restrict__ outp, int B, int D) {
    const float invB = 1.f / (float)B;
    const float s0 = g_score[0] * invB;
    const float s1 = g_score[1] * invB;
    const float mx = fmaxf(s0, s1);
    const float e0 = expf(s0 - mx);
    const float e1 = expf(s1 - mx);
    const float beta0 = e0 / (e0 + e1);
    const float beta1 = 1.f - beta0;

    const int idx = blockIdx.x * blockDim.x + threadIdx.x;
    const int tot = B * D;
    if (idx < tot) {
        const int b = idx / D;
        const int d = idx - b * D;
        const float* mr = g_means + (size_t)b * 2 * D;
        outp[idx] = mr[d] * beta0 + mr[D + d] * beta1;
    }
}

// ---------------------------------------------------------------------------
extern "C" void kernel_launch(void* const* d_in, const int* in_sizes, int n_in,
                              void* d_out, int out_size) {
    const float* x   = (const float*)d_in[0];   // out [N, D] fp32
    const int*   z   = (const int*)d_in[1];     // z   [N] int32/int64
    const int*   bat = (const int*)d_in[2];     // batch [N] sorted int32/int64
    const float* W1  = (const float*)d_in[3];   // [D, A]
    const float* b1  = (const float*)d_in[4];   // [A]
    const float* q   = (const float*)d_in[5];   // [A, 1]

    const int N = in_sizes[1];
    const int D = in_sizes[0] / N;
    const int A = in_sizes[4];
    const int B = out_size / D;
    const int Dp = (D + 3) & ~3;

    const int tgrid = min((A * Dp + 255) / 256, 256);
    detect_transpose_kernel<<<tgrid, 256>>>(bat, N, W1, D, Dp, A);  // launch 1
    bounds_mask_kernel<<<(N + 255) / 256, 256>>>(bat, z, N, B);     // launch 2

    const int PQ = D >> 1;                                   // float4s per pair
    const bool fast = ((D & 1) == 0) && (N <= MAXN) && (D <= MAXD) && (PQ <= 96);
    if (fast) {                                              // launch 3
        if (PQ == 75) seg_mean_pair<75><<<B, 96>>>(x, D, PQ);
        else          seg_mean_pair<0><<<B, ((PQ + 31) / 32) * 32>>>(x, D, PQ);
    } else {
        int tpb = ((D + 31) / 32) * 32;
        if (tpb > 1024) tpb = 1024;
        seg_mean_scalar_kernel<<<B, tpb>>>(x, z, D);
    }

    const int nblk2 = (B + SGPB - 1) / SGPB;
    const size_t shmem = (size_t)SVPB * Dp * sizeof(float);
    score_kernel<<<nblk2, 128, shmem>>>(b1, q, D, Dp, A, B, nblk2);  // 4 (profiled)

    if ((D & 1) == 0) {                                      // launch 5
        const int D2 = D >> 1;
        int tpb = ((D2 + 31) / 32) * 32;
        if (tpb > 1024) tpb = 1024;
        combine_graph_kernel<<<B, tpb>>>((float2*)d_out, D);
    } else {
        const int tot = B * D;
        combine_scalar_kernel<<<(tot + 255) / 256, 256>>>((float*)d_out, B, D);
    }
}

// round 12
// speedup vs baseline: 1.3648x; 1.0424x over previous
#include <cuda_runtime.h>

// ---------------------------------------------------------------------------
// RealVirtualAttention:
//   1) masked segment-mean over sorted batch (real vs virtual nodes) -> [B,2,D]
//   2) HAN semantic attention: score_m = sum_b q^T tanh(W1^T x_{b,m} + b1)
//      beta = softmax(score / B)
//   3) out[b] = beta0 * mean_real[b] + beta1 * mean_virtual[b]
// ---------------------------------------------------------------------------

#define VIRTUAL_Z 100
#define MAXB 8192
#define MAXD 256
#define MAXA 512
#define MAXN (1 << 22)             // mask capacity: 4M rows (16 MB)
#define SGPB 4                     // graphs per block in score kernel
#define SVPB (2*SGPB)              // vectors per block (8)

typedef unsigned long long u64;

__device__ float g_means[(size_t)MAXB * 2 * MAXD];   // [B][2][D] means
__device__ float g_w1b[(size_t)MAXA * MAXD];         // W1 blocked: [d/4][aa][4]
__device__ float g_part[(MAXB / SGPB) * 2 + 2];      // per-block partial scores
__device__ float g_score[2];
__device__ int   g_is64;
__device__ int   g_bounds[MAXB + 1];                 // row range per graph
__device__ unsigned int g_count;                     // score-block completion ctr
__device__ float g_maskf[MAXN];                      // 1.0 = real, 0.0 = virtual

// ---- packed f32x2 / misc helpers -------------------------------------------
__device__ __forceinline__ u64 ld64cs(const float* p) {
    u64 v;
    asm volatile("ld.global.cs.b64 %0, [%1];" : "=l"(v) : "l"(p));
    return v;
}
__device__ __forceinline__ void ld128cs(const float* p, u64& a, u64& b) {
    asm volatile("ld.global.cs.v2.b64 {%0, %1}, [%2];"
                 : "=l"(a), "=l"(b) : "l"(p));
}
__device__ __forceinline__ void add2(u64& a, u64 b) {
    asm("add.rn.f32x2 %0, %1, %2;" : "=l"(a) : "l"(a), "l"(b));
}
__device__ __forceinline__ void fma2(u64& a, u64 m, u64 v) {
    asm("fma.rn.f32x2 %0, %1, %2, %3;" : "=l"(a) : "l"(m), "l"(v), "l"(a));
}
__device__ __forceinline__ u64 dup2(float m) {
    u64 r;
    asm("mov.b64 %0, {%1, %1};" : "=l"(r) : "f"(m));
    return r;
}
__device__ __forceinline__ float2 unpk(u64 v) {
    float2 r;
    asm("mov.b64 {%0, %1}, %2;" : "=f"(r.x), "=f"(r.y) : "l"(v));
    return r;
}
__device__ __forceinline__ float tanh_fast(float x) {
    float y;
    asm("tanh.approx.f32 %0, %1;" : "=f"(y) : "f"(x));
    return y;
}

// ---------------------------------------------------------------------------
// Launch 1 (fused): dtype detect + W1 blocked transpose.
// Detect int32 vs int64 (jax silently downcasts int64 -> int32 when x64 is
// disabled): viewing as int32, odd slots near the end are 0 iff int64.
// Blocked transpose: g_w1b[(d/4)*A*4 + aa*4 + (d%4)] = W1[d*A + aa]
// (zero-padded for d in [D, Dp)). In the score kernel, thread aa's float4
// for chunk d sits at aa*16 bytes within the chunk slab -> a warp's LDG.128
// covers 512 CONTIGUOUS bytes (4 wavefronts, vs 32 strided lines before).
// ---------------------------------------------------------------------------
__global__ void detect_transpose_kernel(const int* __restrict__ bat32, int N,
                                        const float* __restrict__ W1,
                                        int D, int Dp, int A) {
    if (blockIdx.x == 0 && threadIdx.x == 0) {
        int is64 = 1;
        int idx = N - 1;
        if ((idx & 1) == 0) idx--;
        for (int k = 0; k < 8 && idx >= 1; k++, idx -= 2) {
            if (bat32[idx] != 0) { is64 = 0; break; }
        }
        g_is64 = is64;
        g_count = 0u;
    }
    const int total = A * Dp;
    for (int i = blockIdx.x * blockDim.x + threadIdx.x; i < total;
         i += gridDim.x * blockDim.x) {
        // i enumerates (d, aa) with aa fastest -> coalesced reads of W1.
        const int d  = i / A;
        const int aa = i - d * A;
        const int out = (d >> 2) * (A * 4) + aa * 4 + (d & 3);
        g_w1b[out] = (d < D) ? W1[(size_t)d * A + aa] : 0.f;
    }
}

// ---------------------------------------------------------------------------
// Launch 2 (fused): bounds + mask, one pass over batch and z:
//   g_bounds[b] = first row index with batch >= b
//   g_maskf[i]  = (z[i] != VIRTUAL_Z) ? 1.f : 0.f
// ---------------------------------------------------------------------------
__global__ void bounds_mask_kernel(const int* __restrict__ bat32,
                                   const int* __restrict__ z32,
                                   int N, int B) {
    const int s = g_is64;
    const int i = blockIdx.x * blockDim.x + threadIdx.x;
    if (i >= N) return;

    g_maskf[i] = (z32[(size_t)i << s] != VIRTUAL_Z) ? 1.f : 0.f;

    const int cur  = bat32[(size_t)i << s];
    const int prev = (i == 0) ? -1 : bat32[(size_t)(i - 1) << s];
    for (int b = prev + 1; b <= cur; b++) g_bounds[b] = i;
    if (i == N - 1) {
        for (int b = cur + 1; b <= B; b++) g_bounds[b] = N;
    }
}

// ---------------------------------------------------------------------------
// Kernel 1 (hot, R7-proven, FROZEN): row-PAIR float4 streaming. Two rows =
// D/2 float4s; pair blocks are 16B aligned at even row indices. Thread t
// owns float4 #t: 16-row (8-pair) chunks give 8 LDG.128 in flight (128 B)
// per thread. Packed f32x2 masked accumulation; SMEM transpose undoes the
// feature permutation; scalar prologue/tail. sv = st - sr.
// ---------------------------------------------------------------------------
template <int PQS>   // PQ = D/2 (float4s per pair block); 0 = runtime
__global__ void seg_mean_pair(const float* __restrict__ x, int D, int PQrt) {
    const int PQ = (PQS > 0) ? PQS : PQrt;
    const int b = blockIdx.x;
    const int start = g_bounds[b];
    const int end   = g_bounds[b + 1];
    const int t   = threadIdx.x;
    const bool act = (t < PQ);
    const int  tc  = act ? t : (PQ - 1);        // clamp: no divergence

    const bool lowR0  = (4 * tc + 1 < D);       // low packed half in first row?
    const bool highR0 = (4 * tc + 3 < D);       // high packed half in first row?

    u64 stL = 0ull, srL = 0ull, stH = 0ull, srH = 0ull;  // pair-loop accs
    u64 stP = 0ull, srP = 0ull;                 // scalar-row accs (feat 2tc,2tc+1)
    float crf = 0.f;

    int i = start;
    // Scalar prologue: align i to a multiple of 4.
    for (; i < end && (i & 3); i++) {
        const float m = g_maskf[i];
        const u64 v = ld64cs(x + (size_t)i * D + 2 * tc);
        add2(stP, v); fma2(srP, dup2(m), v); crf += m;
    }

    const float* xp = x + (size_t)i * D + 4 * tc;
    // Main: 16 rows = 8 pairs per iteration.
    for (; i + 16 <= end; i += 16, xp += (size_t)16 * D) {
        float4 mq[4];
        #pragma unroll
        for (int j = 0; j < 4; j++)
            mq[j] = *reinterpret_cast<const float4*>(&g_maskf[i + 4 * j]);
        u64 vl[8], vh[8];
        #pragma unroll
        for (int k = 0; k < 8; k++)
            ld128cs(xp + (size_t)2 * k * D, vl[k], vh[k]);

        #pragma unroll
        for (int k = 0; k < 8; k++) {
            const float4 mk = mq[k >> 1];
            const float m0 = (k & 1) ? mk.z : mk.x;
            const float m1 = (k & 1) ? mk.w : mk.y;
            const u64 d0 = dup2(m0), d1 = dup2(m1);
            add2(stL, vl[k]); fma2(srL, lowR0  ? d0 : d1, vl[k]);
            add2(stH, vh[k]); fma2(srH, highR0 ? d0 : d1, vh[k]);
        }
        crf += mq[0].x + mq[0].y + mq[0].z + mq[0].w
             + mq[1].x + mq[1].y + mq[1].z + mq[1].w
             + mq[2].x + mq[2].y + mq[2].z + mq[2].w
             + mq[3].x + mq[3].y + mq[3].z + mq[3].w;
    }
    // Tail pairs (i still even).
    for (; i + 2 <= end; i += 2, xp += (size_t)2 * D) {
        const float m0 = g_maskf[i];
        const float m1 = g_maskf[i + 1];
        u64 a, c;
        ld128cs(xp, a, c);
        const u64 d0 = dup2(m0), d1 = dup2(m1);
        add2(stL, a); fma2(srL, lowR0  ? d0 : d1, a);
        add2(stH, c); fma2(srH, highR0 ? d0 : d1, c);
        crf += m0 + m1;
    }
    // Final odd row.
    for (; i < end; i++) {
        const float m = g_maskf[i];
        const u64 v = ld64cs(x + (size_t)i * D + 2 * tc);
        add2(stP, v); fma2(srP, dup2(m), v); crf += m;
    }

    // Undo the pair-block feature permutation via SMEM.
    __shared__ float sst[2 * MAXD], ssr[2 * MAXD];
    if (act) {
        const float2 l = unpk(stL), h = unpk(stH);
        sst[4 * t + 0] = l.x; sst[4 * t + 1] = l.y;
        sst[4 * t + 2] = h.x; sst[4 * t + 3] = h.y;
        const float2 rl = unpk(srL), rh = unpk(srH);
        ssr[4 * t + 0] = rl.x; ssr[4 * t + 1] = rl.y;
        ssr[4 * t + 2] = rh.x; ssr[4 * t + 3] = rh.y;
    }
    __syncthreads();

    if (act) {
        const float2 pst = unpk(stP), psr = unpk(srP);
        const int f0 = 2 * t, f1 = 2 * t + 1;
        const float st0 = sst[f0] + sst[f0 + D] + pst.x;
        const float st1 = sst[f1] + sst[f1 + D] + pst.y;
        const float sr0 = ssr[f0] + ssr[f0 + D] + psr.x;
        const float sr1 = ssr[f1] + ssr[f1 + D] + psr.y;
        const float cr = crf;
        const float cv = (float)(end - start) - cr;
        const float ir = 1.f / fmaxf(cr, 1.f);
        const float iv = 1.f / fmaxf(cv, 1.f);
        float* mr = g_means + (size_t)b * 2 * D;
        reinterpret_cast<float2*>(mr)[t]     = make_float2(sr0 * ir, sr1 * ir);
        reinterpret_cast<float2*>(mr + D)[t] = make_float2((st0 - sr0) * iv,
                                                           (st1 - sr1) * iv);
    }
}

// Scalar fallback for odd D or PQ > 96 (not hit for this problem's shapes).
__global__ void seg_mean_scalar_kernel(const float* __restrict__ x,
                                       const int*   __restrict__ z32,
                                       int D) {
    const int b = blockIdx.x;
    const int s = g_is64;
    const int start = g_bounds[b];
    const int end   = g_bounds[b + 1];
    const int t = threadIdx.x;

    float srs = 0.f, svs = 0.f;
    int cr = 0, cv = 0;
    for (int i = start; i < end; i++) {
        const int zz = z32[(size_t)i << s];
        float v = (t < D) ? x[(size_t)i * D + t] : 0.f;
        if (zz != VIRTUAL_Z) { srs += v; cr++; } else { svs += v; cv++; }
    }
    if (t < D) {
        float* mr = g_means + (size_t)b * 2 * D;
        mr[t]     = srs / (float)max(cr, 1);
        mr[D + t] = svs / (float)max(cv, 1);
    }
}

// ---------------------------------------------------------------------------
// Kernel 2: semantic attention scores. Measured-best block shape (128 thr,
// SGPB=4). W1 comes from the BLOCKED transpose g_w1b: one LDG.128 per 4-d
// chunk, fully coalesced across the warp (512 contiguous bytes). sx reads
// are warp-broadcast LDS.128. tanh via tanh.approx.f32 (MUFU).
// Last block (atomic-counter elect) does the fixed-order final reduction.
// ---------------------------------------------------------------------------
__global__ void score_kernel(const float* __restrict__ b1,
                             const float* __restrict__ q,
                             int D, int Dp, int A, int B, int nblk) {
    extern __shared__ float sx[];   // [SVPB][Dp]
    __shared__ float r0[4], r1[4];
    __shared__ int   s_last;

    const int b0 = blockIdx.x * SGPB;
    const int nv = min(SVPB, 2 * (B - b0));   // valid vectors in this block

    for (int i = threadIdx.x; i < SVPB * Dp; i += blockDim.x) {
        const int v = i / Dp;
        const int d = i - v * Dp;
        float val = 0.f;
        if (v < nv && d < D) val = g_means[((size_t)b0 * 2 + v) * D + d];
        sx[i] = val;
    }
    if (threadIdx.x == 0) s_last = 0;
    __syncthreads();

    const int warp = threadIdx.x >> 5;
    const int lane = threadIdx.x & 31;
    const int A4 = A * 4;                      // floats per chunk slab
    float t0 = 0.f, t1 = 0.f;

    for (int aa = threadIdx.x; aa < A; aa += blockDim.x) {
        float acc[SVPB];
        const float bb = b1[aa];
        const float qa = q[aa];
        #pragma unroll
        for (int v = 0; v < SVPB; v++) acc[v] = bb;

        const float* wp = g_w1b + aa * 4;      // thread's float4 within slab 0
        for (int d = 0; d < Dp; d += 4, wp += A4) {
            const float4 w = *reinterpret_cast<const float4*>(wp);
            #pragma unroll
            for (int v = 0; v < SVPB; v++) {
                const float4 xv = *reinterpret_cast<const float4*>(&sx[v * Dp + d]);
                acc[v] = fmaf(xv.x, w.x, acc[v]);
                acc[v] = fmaf(xv.y, w.y, acc[v]);
                acc[v] = fmaf(xv.z, w.z, acc[v]);
                acc[v] = fmaf(xv.w, w.w, acc[v]);
            }
        }

        #pragma unroll
        for (int v = 0; v < SVPB; v++) {
            if (v < nv) {
                const float tv = tanh_fast(acc[v]) * qa;
                if (v & 1) t1 += tv; else t0 += tv;
            }
        }
    }

    #pragma unroll
    for (int off = 16; off; off >>= 1) {
        t0 += __shfl_down_sync(0xffffffffu, t0, off);
        t1 += __shfl_down_sync(0xffffffffu, t1, off);
    }
    if (lane == 0) { r0[warp] = t0; r1[warp] = t1; }
    __syncthreads();

    if (threadIdx.x == 0) {
        float s0 = r0[0] + r0[1] + r0[2] + r0[3];
        float s1 = r1[0] + r1[1] + r1[2] + r1[3];
        g_part[2 * blockIdx.x + 0] = s0;
        g_part[2 * blockIdx.x + 1] = s1;
        __threadfence();
        const unsigned int done = atomicAdd(&g_count, 1u);
        if (done == (unsigned int)(nblk - 1)) s_last = 1;
    }
    __syncthreads();

    if (s_last && warp == 0) {
        float a0 = 0.f, a1 = 0.f;
        for (int i = lane; i < nblk; i += 32) {
            a0 += g_part[2 * i + 0];
            a1 += g_part[2 * i + 1];
        }
        #pragma unroll
        for (int off = 16; off; off >>= 1) {
            a0 += __shfl_down_sync(0xffffffffu, a0, off);
            a1 += __shfl_down_sync(0xffffffffu, a1, off);
        }
        if (lane == 0) { g_score[0] = a0; g_score[1] = a1; }
    }
}

// ---------------------------------------------------------------------------
// Kernel 3: beta = softmax(score / B); out[b,d] = beta0*mean_r + beta1*mean_v
// One block per graph: no integer division, float2 I/O.
// ---------------------------------------------------------------------------
__global__ void combine_graph_kernel(float2* __restrict__ outp, int D) {
    const float invB = 1.f / (float)gridDim.x;
    const float s0 = g_score[0] * invB;
    const float s1 = g_score[1] * invB;
    const float mx = fmaxf(s0, s1);
    const float e0 = expf(s0 - mx);
    const float e1 = expf(s1 - mx);
    const float beta0 = e0 / (e0 + e1);
    const float beta1 = 1.f - beta0;

    const int b  = blockIdx.x;
    const int t  = threadIdx.x;
    const int D2 = D >> 1;
    if (t < D2) {
        const float* mrow = g_means + (size_t)b * 2 * D;
        const float2 r = reinterpret_cast<const float2*>(mrow)[t];
        const float2 v = reinterpret_cast<const float2*>(mrow + D)[t];
        outp[(size_t)b * D2 + t] = make_float2(r.x * beta0 + v.x * beta1,
                                               r.y * beta0 + v.y * beta1);
    }
}

__global__ void combine_scalar_kernel(float* __restrict__ outp, int B, int D) {
    const float invB = 1.f / (float)B;
    const float s0 = g_score[0] * invB;
    const float s1 = g_score[1] * invB;
    const float mx = fmaxf(s0, s1);
    const float e0 = expf(s0 - mx);
    const float e1 = expf(s1 - mx);
    const float beta0 = e0 / (e0 + e1);
    const float beta1 = 1.f - beta0;

    const int idx = blockIdx.x * blockDim.x + threadIdx.x;
    const int tot = B * D;
    if (idx < tot) {
        const int b = idx / D;
        const int d = idx - b * D;
        const float* mr = g_means + (size_t)b * 2 * D;
        outp[idx] = mr[d] * beta0 + mr[D + d] * beta1;
    }
}

// ---------------------------------------------------------------------------
extern "C" void kernel_launch(void* const* d_in, const int* in_sizes, int n_in,
                              void* d_out, int out_size) {
    const float* x   = (const float*)d_in[0];   // out [N, D] fp32
    const int*   z   = (const int*)d_in[1];     // z   [N] int32/int64
    const int*   bat = (const int*)d_in[2];     // batch [N] sorted int32/int64
    const float* W1  = (const float*)d_in[3];   // [D, A]
    const float* b1  = (const float*)d_in[4];   // [A]
    const float* q   = (const float*)d_in[5];   // [A, 1]

    const int N = in_sizes[1];
    const int D = in_sizes[0] / N;
    const int A = in_sizes[4];
    const int B = out_size / D;
    const int Dp = (D + 3) & ~3;

    const int tgrid = min((A * Dp + 255) / 256, 256);
    detect_transpose_kernel<<<tgrid, 256>>>(bat, N, W1, D, Dp, A);  // launch 1
    bounds_mask_kernel<<<(N + 255) / 256, 256>>>(bat, z, N, B);     // launch 2

    const int PQ = D >> 1;                                   // float4s per pair
    const bool fast = ((D & 1) == 0) && (N <= MAXN) && (D <= MAXD) && (PQ <= 96);
    if (fast) {                                              // launch 3
        if (PQ == 75) seg_mean_pair<75><<<B, 96>>>(x, D, PQ);
        else          seg_mean_pair<0><<<B, ((PQ + 31) / 32) * 32>>>(x, D, PQ);
    } else {
        int tpb = ((D + 31) / 32) * 32;
        if (tpb > 1024) tpb = 1024;
        seg_mean_scalar_kernel<<<B, tpb>>>(x, z, D);
    }

    const int nblk2 = (B + SGPB - 1) / SGPB;
    const size_t shmem = (size_t)SVPB * Dp * sizeof(float);
    score_kernel<<<nblk2, 128, shmem>>>(b1, q, D, Dp, A, B, nblk2);  // 4 (profiled)

    if ((D & 1) == 0) {                                      // launch 5
        const int D2 = D >> 1;
        int tpb = ((D2 + 31) / 32) * 32;
        if (tpb > 1024) tpb = 1024;
        combine_graph_kernel<<<B, tpb>>>((float2*)d_out, D);
    } else {
        const int tot = B * D;
        combine_scalar_kernel<<<(tot + 255) / 256, 256>>>((float*)d_out, B, D);
    }
}